// round 11
// baseline (speedup 1.0000x reference)
#include <cuda_runtime.h>
#include <cstdint>

// Problem constants
#define B_    2
#define T_    2048
#define C_    1024
#define NH_   16
#define HD_   64
#define M_    (B_ * T_)     // 4096
#define NQKV_ (3 * C_)      // 3072

// Scratch (device globals: allocation-free)
__device__ float g_qkv[(size_t)M_ * NQKV_];      // qkv activations (tf32 bits, d-permuted)
__device__ float g_att[(size_t)M_ * C_];         // attention out  (tf32 bits, k-permuted)
__device__ float g_xt [(size_t)M_ * C_];         // x   -> tf32, k-permuted
__device__ float g_wqkvt[(size_t)C_ * NQKV_];    // Wqkv^T -> tf32 [N][K], k-permuted
__device__ float g_wprojt[(size_t)C_ * C_];      // Wproj^T -> tf32 [N][K], k-permuted

// ---------------------------------------------------------------------------
// helpers
// ---------------------------------------------------------------------------
__device__ __forceinline__ uint32_t f2tf32(float f) {
    uint32_t u;
    asm volatile("cvt.rna.tf32.f32 %0, %1;" : "=r"(u) : "f"(f));
    return u;
}
__device__ __forceinline__ float tf32f(float f) { return __uint_as_float(f2tf32(f)); }
__device__ __forceinline__ float ex2f(float x) {
    float y;
    asm volatile("ex2.approx.ftz.f32 %0, %1;" : "=f"(y) : "f"(x));
    return y;
}
__device__ __forceinline__ void cp16(uint32_t dsm, const void* src) {
    asm volatile("cp.async.ca.shared.global [%0], [%1], 16;" :: "r"(dsm), "l"(src));
}
#define CP_COMMIT() asm volatile("cp.async.commit_group;")
#define CP_WAIT0()  asm volatile("cp.async.wait_group 0;")

// within-8 k-permutation: storage position of true k.  p(k)=((k&3)<<1)|(k>>2)
// -> mma slots (t4, t4+4) sit at adjacent storage positions (2*t4, 2*t4+1).
__device__ __host__ __forceinline__ int perm8(int k) { return ((k & 3) << 1) | (k >> 2); }

#define MMA_TF32(d, a0,a1,a2,a3, b0,b1)                                   \
    asm volatile("mma.sync.aligned.m16n8k8.row.col.f32.tf32.tf32.f32 "    \
        "{%0,%1,%2,%3}, {%4,%5,%6,%7}, {%8,%9}, {%0,%1,%2,%3};"           \
        : "+f"((d)[0]), "+f"((d)[1]), "+f"((d)[2]), "+f"((d)[3])          \
        : "r"(a0), "r"(a1), "r"(a2), "r"(a3), "r"(b0), "r"(b1))

// ---------------------------------------------------------------------------
// cvt kernels: fp32 -> tf32 with within-8 k-permute; weights also transposed.
// ---------------------------------------------------------------------------
__global__ void cvt_x_perm(const float4* __restrict__ in,
                           float4* __restrict__ out, int n8) {
    int i = blockIdx.x * blockDim.x + threadIdx.x;
    if (i < n8) {
        float4 u = in[2*i], v = in[2*i + 1];
        float4 o0, o1;   // positions 0..3 <- k {0,4,1,5}; 4..7 <- k {2,6,3,7}
        o0.x = tf32f(u.x); o0.y = tf32f(v.x); o0.z = tf32f(u.y); o0.w = tf32f(v.y);
        o1.x = tf32f(u.z); o1.y = tf32f(v.z); o1.z = tf32f(u.w); o1.w = tf32f(v.w);
        out[2*i] = o0; out[2*i + 1] = o1;
    }
}

// W [K][N] -> W' [N][K] (k-permuted within 8-groups), tiled via smem.
__global__ void cvt_transpose_perm(const float* __restrict__ in,
                                   float* __restrict__ out, int K, int N) {
    __shared__ float t[32][33];
    const int k0 = blockIdx.y * 32, n0 = blockIdx.x * 32;
    const int tx = threadIdx.x, ty = threadIdx.y;
#pragma unroll
    for (int i = 0; i < 4; i++)
        t[ty + 8*i][tx] = in[(size_t)(k0 + ty + 8*i) * N + n0 + tx];
    __syncthreads();
    const int kp = (tx & ~7) | perm8(tx & 7);
#pragma unroll
    for (int i = 0; i < 4; i++) {
        int n = ty + 8*i;
        out[(size_t)(n0 + n) * K + k0 + kp] = tf32f(t[tx][n]);
    }
}

// ---------------------------------------------------------------------------
// TF32 GEMM + bias (unchanged from R9).  C[M,N] = A[M,K] @ B'[N,K]^T + bias.
// 128 threads / 4 warps, warp tile 64x64, 128x128x32 block tile, 2-stage
// cp.async, single barrier per k-tile.
// ---------------------------------------------------------------------------
#define GST 40
#define STG (128 * GST)                    // floats per operand per stage
#define GEMM_SMEM (2 * 2 * STG * 4)        // 81920 B

template<bool PERM_OUT>
__global__ __launch_bounds__(128, 2)
void gemm_tc(const float* __restrict__ A, const float* __restrict__ Bm,
             const float* __restrict__ bias, float* __restrict__ Cm,
             int M, int N, int K) {
    extern __shared__ float smg[];

    const int tid  = threadIdx.x;
    const int lane = tid & 31, warp = tid >> 5;
    const int wm = warp >> 1, wn = warp & 1;     // 2x2 warp grid, 64x64 tiles
    const int g  = lane >> 2, t4 = lane & 3;
    const int row0 = blockIdx.y * 128, col0 = blockIdx.x * 128;

    const uint32_t sbase = (uint32_t)__cvta_generic_to_shared(smg);

    auto issue = [&](int kt) {
        const int buf = kt & 1;
        const uint32_t sA = sbase + (uint32_t)(buf * 2 * STG) * 4;
        const uint32_t sB = sA + (uint32_t)STG * 4;
#pragma unroll
        for (int i = 0; i < 8; i++) {
            int idx = tid + 128 * i;
            int r = idx >> 3, kc = (idx & 7) << 2;
            cp16(sA + (uint32_t)(r * GST + kc) * 4,
                 &A[(size_t)(row0 + r) * K + kt * 32 + kc]);
        }
#pragma unroll
        for (int i = 0; i < 8; i++) {
            int idx = tid + 128 * i;
            int r = idx >> 3, kc = (idx & 7) << 2;
            cp16(sB + (uint32_t)(r * GST + kc) * 4,
                 &Bm[(size_t)(col0 + r) * K + kt * 32 + kc]);
        }
    };

    float acc[4][8][4];
#pragma unroll
    for (int mt = 0; mt < 4; mt++)
#pragma unroll
        for (int nt = 0; nt < 8; nt++)
#pragma unroll
            for (int c = 0; c < 4; c++) acc[mt][nt][c] = 0.f;

    const int KT = K >> 5;
    issue(0); CP_COMMIT();

    for (int kt = 0; kt < KT; kt++) {
        CP_WAIT0();          // tile kt landed (issued last iteration)
        __syncthreads();     // all warps past compute(kt-1) on the other buffer
        if (kt + 1 < KT) { issue(kt + 1); CP_COMMIT(); }

        const float* Ab = smg + (kt & 1) * 2 * STG;
        const float* Bb = Ab + STG;

#pragma unroll
        for (int kk = 0; kk < 32; kk += 8) {
            uint32_t ra[4][4], rb[8][2];
#pragma unroll
            for (int mt = 0; mt < 4; mt++) {
                const float* ap = Ab + (wm*64 + mt*16 + g) * GST + kk + 2*t4;
                float2 p0 = *reinterpret_cast<const float2*>(ap);
                float2 p1 = *reinterpret_cast<const float2*>(ap + 8*GST);
                ra[mt][0] = __float_as_uint(p0.x);
                ra[mt][2] = __float_as_uint(p0.y);
                ra[mt][1] = __float_as_uint(p1.x);
                ra[mt][3] = __float_as_uint(p1.y);
            }
#pragma unroll
            for (int nt = 0; nt < 8; nt++) {
                const float* bp = Bb + (wn*64 + nt*8 + g) * GST + kk + 2*t4;
                float2 pb = *reinterpret_cast<const float2*>(bp);
                rb[nt][0] = __float_as_uint(pb.x);
                rb[nt][1] = __float_as_uint(pb.y);
            }
#pragma unroll
            for (int mt = 0; mt < 4; mt++)
#pragma unroll
                for (int nt = 0; nt < 8; nt++)
                    MMA_TF32(acc[mt][nt], ra[mt][0], ra[mt][1], ra[mt][2],
                             ra[mt][3], rb[nt][0], rb[nt][1]);
        }
    }

    // epilogue: + bias (true columns); PERM_OUT scatters within 8-groups
    const int pos0 = perm8(2 * t4);
#pragma unroll
    for (int mt = 0; mt < 4; mt++) {
        const int rA = row0 + wm*64 + mt*16 + g;
        const int rB = rA + 8;
#pragma unroll
        for (int nt = 0; nt < 8; nt++) {
            const int cb = col0 + wn*64 + nt*8;
            const int c  = cb + 2*t4;
            const float b0 = bias[c], b1 = bias[c + 1];
            float v0 = acc[mt][nt][0] + b0, v1 = acc[mt][nt][1] + b1;
            float v2 = acc[mt][nt][2] + b0, v3 = acc[mt][nt][3] + b1;
            if (PERM_OUT) {
                Cm[(size_t)rA * N + cb + pos0]     = tf32f(v0);
                Cm[(size_t)rA * N + cb + pos0 + 2] = tf32f(v1);
                Cm[(size_t)rB * N + cb + pos0]     = tf32f(v2);
                Cm[(size_t)rB * N + cb + pos0 + 2] = tf32f(v3);
            } else {
                *reinterpret_cast<float2*>(&Cm[(size_t)rA * N + c]) = make_float2(v0, v1);
                *reinterpret_cast<float2*>(&Cm[(size_t)rB * N + c]) = make_float2(v2, v3);
            }
        }
    }
}

// ---------------------------------------------------------------------------
// Tensor-core flash attention, BM=64 / 128 threads / 4 warps -> 110.6 KB smem
// -> 2 CTA/SM (cross-CTA latency hiding for softmax/barriers/cp.async).
// Per-warp structure identical to R9 (16 rows/warp, perm8 dataflow).
// ---------------------------------------------------------------------------
#define QS_ST 72
#define KS_ST 72
#define VS_ST 72
#define PS_ST 72
#define KV_TILE (64 * KS_ST + 64 * VS_ST)
#define ATTN_SMEM ((64*QS_ST + 2*KV_TILE + 64*PS_ST) * 4)   // 110592 B

#define MASKVAL (-6e30f)
#define MINIT   (-1e30f)

__global__ __launch_bounds__(128, 2)
void attn_tc(const float* __restrict__ qkv, float* __restrict__ att) {
    extern __shared__ float sm[];
    float* Qs  = sm;                        // [64][QS_ST]
    float* KV0 = Qs + 64*QS_ST;             // 2 stages of K[64]+V[64]
    float* Ps  = KV0 + 2*KV_TILE;           // [64][PS_ST]

    const int tid  = threadIdx.x;
    const int lane = tid & 31, warp = tid >> 5;
    const int g = lane >> 2, t4 = lane & 3;
    const int qb = gridDim.x - 1 - blockIdx.x;   // heavy tiles first
    const int bh = blockIdx.y;
    const int b = bh >> 4, h = bh & 15;
    const int m0 = qb * 64;
    const int rb = warp * 16;
    const int pos0 = perm8(2 * t4);

    const float* qbase = qkv + ((size_t)b*T_ + m0)*NQKV_ + h*HD_;
    const float* kbase = qkv + (size_t)b*T_*NQKV_ + h*HD_ + C_;
    const float* vbase = kbase + C_;

    const uint32_t skv = (uint32_t)__cvta_generic_to_shared(KV0);

    auto issue = [&](int kvb) {
        const uint32_t sK = skv + (uint32_t)((kvb & 1) * KV_TILE) * 4;
        const uint32_t sV = sK + (uint32_t)(64 * KS_ST) * 4;
        const int jb = kvb * 64;
#pragma unroll
        for (int i = 0; i < 8; i++) {
            int idx = tid + 128 * i;
            int j = idx >> 4, d4 = (idx & 15) << 2;
            cp16(sK + (uint32_t)(j*KS_ST + d4) * 4, &kbase[(size_t)(jb+j)*NQKV_ + d4]);
        }
#pragma unroll
        for (int i = 0; i < 8; i++) {
            int idx = tid + 128 * i;
            int j = idx >> 4, d4 = (idx & 15) << 2;
            cp16(sV + (uint32_t)(j*VS_ST + d4) * 4, &vbase[(size_t)(jb+j)*NQKV_ + d4]);
        }
    };

    issue(0); CP_COMMIT();

    // Q tile: scale by (1/8)*log2(e), re-round, copy-through (already permuted)
    const float qscale = 0.125f * 1.44269504088896340736f;
    for (int idx = tid; idx < 64*16; idx += 128) {
        int r = idx >> 4, d4 = (idx & 15) << 2;
        float4 v = *reinterpret_cast<const float4*>(&qbase[(size_t)r*NQKV_ + d4]);
        float* q = &Qs[r*QS_ST + d4];
        q[0] = tf32f(v.x * qscale);
        q[1] = tf32f(v.y * qscale);
        q[2] = tf32f(v.z * qscale);
        q[3] = tf32f(v.w * qscale);
    }

    float o[8][4];
    float mrow[2] = {MINIT, MINIT}, lrow[2] = {0.f, 0.f};
#pragma unroll
    for (int nt = 0; nt < 8; nt++)
#pragma unroll
        for (int c = 0; c < 4; c++) o[nt][c] = 0.f;

    const int nkv = qb + 1;
    for (int kvb = 0; kvb < nkv; kvb++) {
        const int jb = kvb * 64;
        CP_WAIT0();
        __syncthreads();
        if (kvb + 1 < nkv) { issue(kvb + 1); CP_COMMIT(); }

        const float* Ks = KV0 + (kvb & 1) * KV_TILE;
        const float* Vs = Ks + 64 * KS_ST;

        if (jb > m0 + rb + 15) continue;

        // ---- S = Q' @ K^T (both d-permuted: dot product invariant) ----
        float s[8][4];
#pragma unroll
        for (int nt = 0; nt < 8; nt++)
#pragma unroll
            for (int c = 0; c < 4; c++) s[nt][c] = 0.f;

#pragma unroll
        for (int kk = 0; kk < 64; kk += 8) {
            const float* ap = &Qs[(rb + g)*QS_ST + kk + 2*t4];
            float2 qa0 = *reinterpret_cast<const float2*>(ap);
            float2 qa1 = *reinterpret_cast<const float2*>(ap + 8*QS_ST);
            uint32_t a0 = __float_as_uint(qa0.x), a2 = __float_as_uint(qa0.y);
            uint32_t a1 = __float_as_uint(qa1.x), a3 = __float_as_uint(qa1.y);
#pragma unroll
            for (int nt = 0; nt < 8; nt++) {
                float2 kf = *reinterpret_cast<const float2*>(
                    &Ks[(nt*8 + g)*KS_ST + kk + 2*t4]);
                MMA_TF32(s[nt], a0, a1, a2, a3,
                         __float_as_uint(kf.x), __float_as_uint(kf.y));
            }
        }

        // ---- causal mask (diagonal-crossing tiles only) ----
        if (jb + 63 > m0 + rb) {
            const int r0 = m0 + rb + g, r1 = r0 + 8;
#pragma unroll
            for (int nt = 0; nt < 8; nt++) {
                int cb = jb + nt*8 + 2*t4;
                if (cb     > r0) s[nt][0] = MASKVAL;
                if (cb + 1 > r0) s[nt][1] = MASKVAL;
                if (cb     > r1) s[nt][2] = MASKVAL;
                if (cb + 1 > r1) s[nt][3] = MASKVAL;
            }
        }

        // ---- online softmax (exp2 domain) ----
        float mx0 = MINIT, mx1 = MINIT;
#pragma unroll
        for (int nt = 0; nt < 8; nt++) {
            mx0 = fmaxf(mx0, fmaxf(s[nt][0], s[nt][1]));
            mx1 = fmaxf(mx1, fmaxf(s[nt][2], s[nt][3]));
        }
        mx0 = fmaxf(mx0, __shfl_xor_sync(0xffffffffu, mx0, 1));
        mx0 = fmaxf(mx0, __shfl_xor_sync(0xffffffffu, mx0, 2));
        mx1 = fmaxf(mx1, __shfl_xor_sync(0xffffffffu, mx1, 1));
        mx1 = fmaxf(mx1, __shfl_xor_sync(0xffffffffu, mx1, 2));
        const float mn0 = fmaxf(mrow[0], mx0), mn1 = fmaxf(mrow[1], mx1);
        const float al0 = ex2f(mrow[0] - mn0), al1 = ex2f(mrow[1] - mn1);
        mrow[0] = mn0; mrow[1] = mn1;

        float ls0 = 0.f, ls1 = 0.f;
#pragma unroll
        for (int nt = 0; nt < 8; nt++) {
            s[nt][0] = ex2f(s[nt][0] - mn0);
            s[nt][1] = ex2f(s[nt][1] - mn0);
            s[nt][2] = ex2f(s[nt][2] - mn1);
            s[nt][3] = ex2f(s[nt][3] - mn1);
            ls0 += s[nt][0] + s[nt][1];
            ls1 += s[nt][2] + s[nt][3];
            o[nt][0] *= al0; o[nt][1] *= al0;
            o[nt][2] *= al1; o[nt][3] *= al1;
            // stage P j-permuted (tf32) for LDS.64 PV fragments
            float* p0 = &Ps[(rb + g)*PS_ST + nt*8];
            float* p1 = &Ps[(rb + g + 8)*PS_ST + nt*8];
            p0[pos0]     = tf32f(s[nt][0]);
            p0[pos0 + 2] = tf32f(s[nt][1]);
            p1[pos0]     = tf32f(s[nt][2]);
            p1[pos0 + 2] = tf32f(s[nt][3]);
        }
        ls0 += __shfl_xor_sync(0xffffffffu, ls0, 1);
        ls0 += __shfl_xor_sync(0xffffffffu, ls0, 2);
        ls1 += __shfl_xor_sync(0xffffffffu, ls1, 1);
        ls1 += __shfl_xor_sync(0xffffffffu, ls1, 2);
        lrow[0] = lrow[0]*al0 + ls0;
        lrow[1] = lrow[1]*al1 + ls1;

        __syncwarp();

        // ---- O += P @ V  (A j-permuted storage <-> V natural rows) ----
#pragma unroll
        for (int kk = 0; kk < 64; kk += 8) {
            const float* ap = &Ps[(rb + g)*PS_ST + kk + 2*t4];
            float2 pa0 = *reinterpret_cast<const float2*>(ap);
            float2 pa1 = *reinterpret_cast<const float2*>(ap + 8*PS_ST);
            uint32_t a0 = __float_as_uint(pa0.x), a2 = __float_as_uint(pa0.y);
            uint32_t a1 = __float_as_uint(pa1.x), a3 = __float_as_uint(pa1.y);
#pragma unroll
            for (int nt = 0; nt < 8; nt++) {
                const float* bp = &Vs[(kk + t4)*VS_ST + nt*8 + g];
                MMA_TF32(o[nt], a0, a1, a2, a3,
                         __float_as_uint(bp[0]), __float_as_uint(bp[4*VS_ST]));
            }
        }
    }

    // ---- epilogue: normalize; position-space write == permuted att ----
    const float inv0 = 1.0f / lrow[0], inv1 = 1.0f / lrow[1];
    const size_t r0 = (size_t)b*T_ + m0 + rb + g;
    const size_t r1 = r0 + 8;
#pragma unroll
    for (int nt = 0; nt < 8; nt++) {
        const int c = h*HD_ + nt*8 + 2*t4;
        *reinterpret_cast<float2*>(&att[r0*C_ + c]) =
            make_float2(tf32f(o[nt][0] * inv0), tf32f(o[nt][1] * inv0));
        *reinterpret_cast<float2*>(&att[r1*C_ + c]) =
            make_float2(tf32f(o[nt][2] * inv1), tf32f(o[nt][3] * inv1));
    }
}

// ---------------------------------------------------------------------------
// Launch
// ---------------------------------------------------------------------------
extern "C" void kernel_launch(void* const* d_in, const int* in_sizes, int n_in,
                              void* d_out, int out_size) {
    const float* x     = (const float*)d_in[0];
    const float* Wqkv  = (const float*)d_in[1];
    const float* bqkv  = (const float*)d_in[2];
    const float* Wproj = (const float*)d_in[3];
    const float* bproj = (const float*)d_in[4];
    float* out = (float*)d_out;

    float *qkv_p, *att_p, *xt_p, *wq_p, *wp_p;
    cudaGetSymbolAddress((void**)&qkv_p, g_qkv);
    cudaGetSymbolAddress((void**)&att_p, g_att);
    cudaGetSymbolAddress((void**)&xt_p,  g_xt);
    cudaGetSymbolAddress((void**)&wq_p,  g_wqkvt);
    cudaGetSymbolAddress((void**)&wp_p,  g_wprojt);

    cudaFuncSetAttribute(gemm_tc<true>,
                         cudaFuncAttributeMaxDynamicSharedMemorySize, GEMM_SMEM);
    cudaFuncSetAttribute(gemm_tc<false>,
                         cudaFuncAttributeMaxDynamicSharedMemorySize, GEMM_SMEM);
    cudaFuncSetAttribute(attn_tc,
                         cudaFuncAttributeMaxDynamicSharedMemorySize, ATTN_SMEM);

    // 0) operand prep: x k-permuted; weights transposed [N][K] + k-permuted
    cvt_x_perm<<<(M_*C_/8)/256, 256>>>((const float4*)x, (float4*)xt_p, M_*C_/8);
    {
        dim3 blk(32, 8);
        dim3 gq(NQKV_/32, C_/32);
        cvt_transpose_perm<<<gq, blk>>>(Wqkv, wq_p, C_, NQKV_);
        dim3 gp(C_/32, C_/32);
        cvt_transpose_perm<<<gp, blk>>>(Wproj, wp_p, C_, C_);
    }

    // 1) QKV GEMM -> d-permuted tf32 qkv
    dim3 g1(NQKV_/128, M_/128);
    gemm_tc<true><<<g1, 128, GEMM_SMEM>>>(xt_p, wq_p, bqkv, qkv_p, M_, NQKV_, C_);

    // 2) Flash attention (BM=64, 2 CTA/SM) -> k-permuted tf32 att
    dim3 g2(T_/64, B_*NH_);
    attn_tc<<<g2, 128, ATTN_SMEM>>>(qkv_p, att_p);

    // 3) Output projection -> natural fp32 out
    dim3 g3(C_/128, M_/128);
    gemm_tc<false><<<g3, 128, GEMM_SMEM>>>(att_p, wp_p, bproj, out, M_, C_, C_);
}

// round 13
// speedup vs baseline: 1.2542x; 1.2542x over previous
#include <cuda_runtime.h>
#include <cuda_fp16.h>
#include <cstdint>

// Problem constants
#define B_    2
#define T_    2048
#define C_    1024
#define NH_   16
#define HD_   64
#define M_    (B_ * T_)     // 4096
#define NQKV_ (3 * C_)      // 3072

// Scratch (device globals: allocation-free)
__device__ float  g_qkv[(size_t)M_ * NQKV_];     // qkv (fp32 tf32-bits, d-perm8) for attention
__device__ __half g_att[(size_t)M_ * C_];        // attention out (half, pair-perm8)
__device__ __half g_xh [(size_t)M_ * C_];        // x -> half, pair-perm8
__device__ __half g_wqkvh[(size_t)C_ * NQKV_];   // Wqkv^T -> half [N][K], pair-perm8
__device__ __half g_wprojh[(size_t)C_ * C_];     // Wproj^T -> half [N][K], pair-perm8

// ---------------------------------------------------------------------------
// helpers
// ---------------------------------------------------------------------------
__device__ __forceinline__ uint32_t f2tf32(float f) {
    uint32_t u;
    asm volatile("cvt.rna.tf32.f32 %0, %1;" : "=r"(u) : "f"(f));
    return u;
}
__device__ __forceinline__ float tf32f(float f) { return __uint_as_float(f2tf32(f)); }
__device__ __forceinline__ float ex2f(float x) {
    float y;
    asm volatile("ex2.approx.ftz.f32 %0, %1;" : "=f"(y) : "f"(x));
    return y;
}
__device__ __forceinline__ void cp16(uint32_t dsm, const void* src) {
    asm volatile("cp.async.ca.shared.global [%0], [%1], 16;" :: "r"(dsm), "l"(src));
}
#define CP_COMMIT() asm volatile("cp.async.commit_group;")
#define CP_WAIT0()  asm volatile("cp.async.wait_group 0;")

// within-8 permutation: storage position of true unit k.
__device__ __host__ __forceinline__ int perm8(int k) { return ((k & 3) << 1) | (k >> 2); }

// tf32 warp mma (attention)
#define MMA_TF32(d, a0,a1,a2,a3, b0,b1)                                   \
    asm volatile("mma.sync.aligned.m16n8k8.row.col.f32.tf32.tf32.f32 "    \
        "{%0,%1,%2,%3}, {%4,%5,%6,%7}, {%8,%9}, {%0,%1,%2,%3};"           \
        : "+f"((d)[0]), "+f"((d)[1]), "+f"((d)[2]), "+f"((d)[3])          \
        : "r"(a0), "r"(a1), "r"(a2), "r"(a3), "r"(b0), "r"(b1))

// fp16 warp mma (GEMMs): K=16 per instruction, fp32 accumulate
#define MMA_F16(d, a0,a1,a2,a3, b0,b1)                                    \
    asm volatile("mma.sync.aligned.m16n8k16.row.col.f32.f16.f16.f32 "     \
        "{%0,%1,%2,%3}, {%4,%5,%6,%7}, {%8,%9}, {%0,%1,%2,%3};"           \
        : "+f"((d)[0]), "+f"((d)[1]), "+f"((d)[2]), "+f"((d)[3])          \
        : "r"(a0), "r"(a1), "r"(a2), "r"(a3), "r"(b0), "r"(b1))

// ---------------------------------------------------------------------------
// cvt kernels: fp32 -> half with pair-perm8 within 16-half groups.
//   true k-pair p (halves 2p,2p+1) stored at b32-unit perm8(p).
// ---------------------------------------------------------------------------
__global__ void cvt_x_h(const float4* __restrict__ in,
                        __half2* __restrict__ out, int n16) {
    int i = blockIdx.x * blockDim.x + threadIdx.x;
    if (i < n16) {
        float4 v0 = in[4*i], v1 = in[4*i+1], v2 = in[4*i+2], v3 = in[4*i+3];
        __half2* o = out + 8*i;
        // unit j holds pair ip(j), ip = {0,4,1,5,2,6,3,7}
        o[0] = __floats2half2_rn(v0.x, v0.y);   // pair 0
        o[1] = __floats2half2_rn(v2.x, v2.y);   // pair 4
        o[2] = __floats2half2_rn(v0.z, v0.w);   // pair 1
        o[3] = __floats2half2_rn(v2.z, v2.w);   // pair 5
        o[4] = __floats2half2_rn(v1.x, v1.y);   // pair 2
        o[5] = __floats2half2_rn(v3.x, v3.y);   // pair 6
        o[6] = __floats2half2_rn(v1.z, v1.w);   // pair 3
        o[7] = __floats2half2_rn(v3.z, v3.w);   // pair 7
    }
}

// W [K][N] fp32 -> W' [N][K] half (pair-perm8 within 16-k groups)
__global__ void cvt_transpose_h(const float* __restrict__ in,
                                __half* __restrict__ out, int K, int N) {
    __shared__ float t[32][33];
    const int k0 = blockIdx.y * 32, n0 = blockIdx.x * 32;
    const int tx = threadIdx.x, ty = threadIdx.y;
#pragma unroll
    for (int i = 0; i < 4; i++)
        t[ty + 8*i][tx] = in[(size_t)(k0 + ty + 8*i) * N + n0 + tx];
    __syncthreads();
    const int kpos = (tx & ~15) | (perm8((tx >> 1) & 7) << 1) | (tx & 1);
#pragma unroll
    for (int i = 0; i < 4; i++) {
        int n = ty + 8*i;
        out[(size_t)(n0 + n) * K + k0 + kpos] = __float2half_rn(t[tx][n]);
    }
}

// ---------------------------------------------------------------------------
// FP16 GEMM + bias.  C[M,N] = A[M,K] @ B'[N,K]^T + bias.
// 128 threads / 4 warps, warp tile 64x64, block 128x128x64(k halves),
// m16n8k16, 2-stage cp.async, single barrier per k-tile.
// PERM_OUT: fp32 out, tf32-rounded, element perm8 scatter (attention format).
// ---------------------------------------------------------------------------
#define ST_H 80
#define STG_H (128 * ST_H)                  // halves per operand per stage
#define GEMM_SMEM (2 * 2 * STG_H * 2)       // 81920 B

template<bool PERM_OUT>
__global__ __launch_bounds__(128, 2)
void gemm_fp16(const __half* __restrict__ A, const __half* __restrict__ Bm,
               const float* __restrict__ bias, float* __restrict__ Cm,
               int M, int N, int K) {
    extern __shared__ __half smh[];

    const int tid  = threadIdx.x;
    const int lane = tid & 31, warp = tid >> 5;
    const int wm = warp >> 1, wn = warp & 1;     // 2x2 warp grid, 64x64 tiles
    const int g  = lane >> 2, t4 = lane & 3;
    const int row0 = blockIdx.y * 128, col0 = blockIdx.x * 128;

    const uint32_t sbase = (uint32_t)__cvta_generic_to_shared(smh);

    auto issue = [&](int kt) {
        const int buf = kt & 1;
        const uint32_t sA = sbase + (uint32_t)(buf * 2 * STG_H) * 2;
        const uint32_t sB = sA + (uint32_t)STG_H * 2;
#pragma unroll
        for (int i = 0; i < 8; i++) {
            int idx = tid + 128 * i;
            int r = idx >> 3, s8 = idx & 7;          // 8 halves per cp16
            cp16(sA + (uint32_t)(r * ST_H * 2 + s8 * 16),
                 &A[(size_t)(row0 + r) * K + kt * 64 + s8 * 8]);
        }
#pragma unroll
        for (int i = 0; i < 8; i++) {
            int idx = tid + 128 * i;
            int r = idx >> 3, s8 = idx & 7;
            cp16(sB + (uint32_t)(r * ST_H * 2 + s8 * 16),
                 &Bm[(size_t)(col0 + r) * K + kt * 64 + s8 * 8]);
        }
    };

    float acc[4][8][4];
#pragma unroll
    for (int mt = 0; mt < 4; mt++)
#pragma unroll
        for (int nt = 0; nt < 8; nt++)
#pragma unroll
            for (int c = 0; c < 4; c++) acc[mt][nt][c] = 0.f;

    const int KT = K >> 6;     // 64-k tiles
    issue(0); CP_COMMIT();

    for (int kt = 0; kt < KT; kt++) {
        CP_WAIT0();          // tile kt landed (issued last iteration)
        __syncthreads();     // all warps past compute(kt-1) on the other buffer
        if (kt + 1 < KT) { issue(kt + 1); CP_COMMIT(); }

        const __half* Ab = smh + (kt & 1) * 2 * STG_H;
        const __half* Bb = Ab + STG_H;

#pragma unroll
        for (int kki = 0; kki < 4; kki++) {
            const int kk = kki * 16;                 // half units
            uint2 ral[4], rah[4];                    // {a0,a2}, {a1,a3}
#pragma unroll
            for (int mt = 0; mt < 4; mt++) {
                const __half* ap = Ab + (wm*64 + mt*16 + g) * ST_H + kk + 4*t4;
                ral[mt] = *reinterpret_cast<const uint2*>(ap);
                rah[mt] = *reinterpret_cast<const uint2*>(ap + 8*ST_H);
            }
#pragma unroll
            for (int nt = 0; nt < 8; nt++) {
                uint2 rb = *reinterpret_cast<const uint2*>(
                    Bb + (wn*64 + nt*8 + g) * ST_H + kk + 4*t4);
#pragma unroll
                for (int mt = 0; mt < 4; mt++)
                    MMA_F16(acc[mt][nt], ral[mt].x, rah[mt].x,
                            ral[mt].y, rah[mt].y, rb.x, rb.y);
            }
        }
    }

    // epilogue: + bias (true columns); PERM_OUT scatters elements by perm8
    const int pos0 = perm8(2 * t4);
#pragma unroll
    for (int mt = 0; mt < 4; mt++) {
        const int rA = row0 + wm*64 + mt*16 + g;
        const int rB = rA + 8;
#pragma unroll
        for (int nt = 0; nt < 8; nt++) {
            const int cb = col0 + wn*64 + nt*8;
            const int c  = cb + 2*t4;
            const float b0 = bias[c], b1 = bias[c + 1];
            float v0 = acc[mt][nt][0] + b0, v1 = acc[mt][nt][1] + b1;
            float v2 = acc[mt][nt][2] + b0, v3 = acc[mt][nt][3] + b1;
            if (PERM_OUT) {
                Cm[(size_t)rA * N + cb + pos0]     = tf32f(v0);
                Cm[(size_t)rA * N + cb + pos0 + 2] = tf32f(v1);
                Cm[(size_t)rB * N + cb + pos0]     = tf32f(v2);
                Cm[(size_t)rB * N + cb + pos0 + 2] = tf32f(v3);
            } else {
                *reinterpret_cast<float2*>(&Cm[(size_t)rA * N + c]) = make_float2(v0, v1);
                *reinterpret_cast<float2*>(&Cm[(size_t)rB * N + c]) = make_float2(v2, v3);
            }
        }
    }
}

// ---------------------------------------------------------------------------
// Tensor-core flash attention (R9 internals: tf32, fp32 d-perm8 qkv, BM=128).
// Epilogue stages O through smem at TRUE d positions, then repacks into the
// half pair-perm8 layout the fp16 proj GEMM consumes.
// ---------------------------------------------------------------------------
#define QS_ST 72
#define KS_ST 72
#define VS_ST 72
#define PS_ST 72
#define KV_TILE (64 * KS_ST + 64 * VS_ST)
#define ATTN_SMEM ((128*QS_ST + 2*KV_TILE + 128*PS_ST) * 4)   // 147456 B

#define MASKVAL (-6e30f)
#define MINIT   (-1e30f)

__global__ __launch_bounds__(256, 1)
void attn_tc(const float* __restrict__ qkv, __half* __restrict__ att) {
    extern __shared__ float sm[];
    float* Qs  = sm;
    float* KV0 = Qs + 128*QS_ST;
    float* Ps  = KV0 + 2*KV_TILE;

    const int tid  = threadIdx.x;
    const int lane = tid & 31, warp = tid >> 5;
    const int g = lane >> 2, t4 = lane & 3;
    const int qb = gridDim.x - 1 - blockIdx.x;   // heavy tiles first
    const int bh = blockIdx.y;
    const int b = bh >> 4, h = bh & 15;
    const int m0 = qb * 128;
    const int rb = warp * 16;
    const int pos0 = perm8(2 * t4);

    const float* qbase = qkv + ((size_t)b*T_ + m0)*NQKV_ + h*HD_;
    const float* kbase = qkv + (size_t)b*T_*NQKV_ + h*HD_ + C_;
    const float* vbase = kbase + C_;

    const uint32_t skv = (uint32_t)__cvta_generic_to_shared(KV0);

    auto issue = [&](int kvb) {
        const uint32_t sK = skv + (uint32_t)((kvb & 1) * KV_TILE) * 4;
        const uint32_t sV = sK + (uint32_t)(64 * KS_ST) * 4;
        const int jb = kvb * 64;
#pragma unroll
        for (int i = 0; i < 4; i++) {
            int idx = tid + 256 * i;
            int j = idx >> 4, d4 = (idx & 15) << 2;
            cp16(sK + (uint32_t)(j*KS_ST + d4) * 4, &kbase[(size_t)(jb+j)*NQKV_ + d4]);
        }
#pragma unroll
        for (int i = 0; i < 4; i++) {
            int idx = tid + 256 * i;
            int j = idx >> 4, d4 = (idx & 15) << 2;
            cp16(sV + (uint32_t)(j*VS_ST + d4) * 4, &vbase[(size_t)(jb+j)*NQKV_ + d4]);
        }
    };

    issue(0); CP_COMMIT();

    const float qscale = 0.125f * 1.44269504088896340736f;
    for (int idx = tid; idx < 128*16; idx += 256) {
        int r = idx >> 4, d4 = (idx & 15) << 2;
        float4 v = *reinterpret_cast<const float4*>(&qbase[(size_t)r*NQKV_ + d4]);
        float* q = &Qs[r*QS_ST + d4];
        q[0] = tf32f(v.x * qscale);
        q[1] = tf32f(v.y * qscale);
        q[2] = tf32f(v.z * qscale);
        q[3] = tf32f(v.w * qscale);
    }

    float o[8][4];
    float mrow[2] = {MINIT, MINIT}, lrow[2] = {0.f, 0.f};
#pragma unroll
    for (int nt = 0; nt < 8; nt++)
#pragma unroll
        for (int c = 0; c < 4; c++) o[nt][c] = 0.f;

    const int nkv = 2*qb + 2;
    for (int kvb = 0; kvb < nkv; kvb++) {
        const int jb = kvb * 64;
        CP_WAIT0();
        __syncthreads();
        if (kvb + 1 < nkv) { issue(kvb + 1); CP_COMMIT(); }

        const float* Ks = KV0 + (kvb & 1) * KV_TILE;
        const float* Vs = Ks + 64 * KS_ST;

        if (jb > m0 + rb + 15) continue;

        float s[8][4];
#pragma unroll
        for (int nt = 0; nt < 8; nt++)
#pragma unroll
            for (int c = 0; c < 4; c++) s[nt][c] = 0.f;

#pragma unroll
        for (int kk = 0; kk < 64; kk += 8) {
            const float* ap = &Qs[(rb + g)*QS_ST + kk + 2*t4];
            float2 qa0 = *reinterpret_cast<const float2*>(ap);
            float2 qa1 = *reinterpret_cast<const float2*>(ap + 8*QS_ST);
            uint32_t a0 = __float_as_uint(qa0.x), a2 = __float_as_uint(qa0.y);
            uint32_t a1 = __float_as_uint(qa1.x), a3 = __float_as_uint(qa1.y);
#pragma unroll
            for (int nt = 0; nt < 8; nt++) {
                float2 kf = *reinterpret_cast<const float2*>(
                    &Ks[(nt*8 + g)*KS_ST + kk + 2*t4]);
                MMA_TF32(s[nt], a0, a1, a2, a3,
                         __float_as_uint(kf.x), __float_as_uint(kf.y));
            }
        }

        if (jb + 63 > m0 + rb) {
            const int r0 = m0 + rb + g, r1 = r0 + 8;
#pragma unroll
            for (int nt = 0; nt < 8; nt++) {
                int cb = jb + nt*8 + 2*t4;
                if (cb     > r0) s[nt][0] = MASKVAL;
                if (cb + 1 > r0) s[nt][1] = MASKVAL;
                if (cb     > r1) s[nt][2] = MASKVAL;
                if (cb + 1 > r1) s[nt][3] = MASKVAL;
            }
        }

        float mx0 = MINIT, mx1 = MINIT;
#pragma unroll
        for (int nt = 0; nt < 8; nt++) {
            mx0 = fmaxf(mx0, fmaxf(s[nt][0], s[nt][1]));
            mx1 = fmaxf(mx1, fmaxf(s[nt][2], s[nt][3]));
        }
        mx0 = fmaxf(mx0, __shfl_xor_sync(0xffffffffu, mx0, 1));
        mx0 = fmaxf(mx0, __shfl_xor_sync(0xffffffffu, mx0, 2));
        mx1 = fmaxf(mx1, __shfl_xor_sync(0xffffffffu, mx1, 1));
        mx1 = fmaxf(mx1, __shfl_xor_sync(0xffffffffu, mx1, 2));
        const float mn0 = fmaxf(mrow[0], mx0), mn1 = fmaxf(mrow[1], mx1);
        const float al0 = ex2f(mrow[0] - mn0), al1 = ex2f(mrow[1] - mn1);
        mrow[0] = mn0; mrow[1] = mn1;

        float ls0 = 0.f, ls1 = 0.f;
#pragma unroll
        for (int nt = 0; nt < 8; nt++) {
            s[nt][0] = ex2f(s[nt][0] - mn0);
            s[nt][1] = ex2f(s[nt][1] - mn0);
            s[nt][2] = ex2f(s[nt][2] - mn1);
            s[nt][3] = ex2f(s[nt][3] - mn1);
            ls0 += s[nt][0] + s[nt][1];
            ls1 += s[nt][2] + s[nt][3];
            o[nt][0] *= al0; o[nt][1] *= al0;
            o[nt][2] *= al1; o[nt][3] *= al1;
            float* p0 = &Ps[(rb + g)*PS_ST + nt*8];
            float* p1 = &Ps[(rb + g + 8)*PS_ST + nt*8];
            p0[pos0]     = tf32f(s[nt][0]);
            p0[pos0 + 2] = tf32f(s[nt][1]);
            p1[pos0]     = tf32f(s[nt][2]);
            p1[pos0 + 2] = tf32f(s[nt][3]);
        }
        ls0 += __shfl_xor_sync(0xffffffffu, ls0, 1);
        ls0 += __shfl_xor_sync(0xffffffffu, ls0, 2);
        ls1 += __shfl_xor_sync(0xffffffffu, ls1, 1);
        ls1 += __shfl_xor_sync(0xffffffffu, ls1, 2);
        lrow[0] = lrow[0]*al0 + ls0;
        lrow[1] = lrow[1]*al1 + ls1;

        __syncwarp();

#pragma unroll
        for (int kk = 0; kk < 64; kk += 8) {
            const float* ap = &Ps[(rb + g)*PS_ST + kk + 2*t4];
            float2 pa0 = *reinterpret_cast<const float2*>(ap);
            float2 pa1 = *reinterpret_cast<const float2*>(ap + 8*PS_ST);
            uint32_t a0 = __float_as_uint(pa0.x), a2 = __float_as_uint(pa0.y);
            uint32_t a1 = __float_as_uint(pa1.x), a3 = __float_as_uint(pa1.y);
#pragma unroll
            for (int nt = 0; nt < 8; nt++) {
                const float* bp = &Vs[(kk + t4)*VS_ST + nt*8 + g];
                MMA_TF32(o[nt], a0, a1, a2, a3,
                         __float_as_uint(bp[0]), __float_as_uint(bp[4*VS_ST]));
            }
        }
    }

    // ---- epilogue: O columns are V-POSITION space (element-perm8 of true d).
    // Position nt*8+2t4   holds true d = nt*8 + t4
    // Position nt*8+2t4+1 holds true d = nt*8 + t4 + 4
    // Stage normalized O into Ps (warp-private rows) at TRUE d, then repack
    // into the half pair-perm8 layout: unit j of 16-group u <- true pair
    // ip(j) = ((j&1)<<2)|(j>>1); lane t4 emits units 2t4, 2t4+1 per group.
    const float inv0 = 1.0f / lrow[0], inv1 = 1.0f / lrow[1];
    {
        __syncwarp();   // done reading Ps as P before overwriting
        float* st0 = &Ps[(rb + g)*PS_ST];
        float* st1 = &Ps[(rb + g + 8)*PS_ST];
#pragma unroll
        for (int nt = 0; nt < 8; nt++) {
            st0[nt*8 + t4]     = o[nt][0] * inv0;
            st0[nt*8 + t4 + 4] = o[nt][1] * inv0;
            st1[nt*8 + t4]     = o[nt][2] * inv1;
            st1[nt*8 + t4 + 4] = o[nt][3] * inv1;
        }
        __syncwarp();

        const size_t r0 = (size_t)b*T_ + m0 + rb + g;
        const size_t r1 = r0 + 8;
#pragma unroll
        for (int u = 0; u < 4; u++) {
            // unit j0=2t4: true halves {2t4, 2t4+1}; j1=2t4+1: {2t4+8, 2t4+9}
            float2 f0 = *reinterpret_cast<const float2*>(&st0[16*u + 2*t4]);
            float2 f1 = *reinterpret_cast<const float2*>(&st0[16*u + 2*t4 + 8]);
            float2 f2 = *reinterpret_cast<const float2*>(&st1[16*u + 2*t4]);
            float2 f3 = *reinterpret_cast<const float2*>(&st1[16*u + 2*t4 + 8]);
            __half2 h0 = __floats2half2_rn(f0.x, f0.y);
            __half2 h1 = __floats2half2_rn(f1.x, f1.y);
            __half2 h2 = __floats2half2_rn(f2.x, f2.y);
            __half2 h3 = __floats2half2_rn(f3.x, f3.y);
            const int hc = h*HD_ + 16*u + 4*t4;   // half col of unit j0
            *reinterpret_cast<__half2*>(&att[r0*C_ + hc])     = h0;
            *reinterpret_cast<__half2*>(&att[r0*C_ + hc + 2]) = h1;
            *reinterpret_cast<__half2*>(&att[r1*C_ + hc])     = h2;
            *reinterpret_cast<__half2*>(&att[r1*C_ + hc + 2]) = h3;
        }
    }
}

// ---------------------------------------------------------------------------
// Launch
// ---------------------------------------------------------------------------
extern "C" void kernel_launch(void* const* d_in, const int* in_sizes, int n_in,
                              void* d_out, int out_size) {
    const float* x     = (const float*)d_in[0];
    const float* Wqkv  = (const float*)d_in[1];
    const float* bqkv  = (const float*)d_in[2];
    const float* Wproj = (const float*)d_in[3];
    const float* bproj = (const float*)d_in[4];
    float* out = (float*)d_out;

    float *qkv_p;
    __half *att_p, *xh_p, *wq_p, *wp_p;
    cudaGetSymbolAddress((void**)&qkv_p, g_qkv);
    cudaGetSymbolAddress((void**)&att_p, g_att);
    cudaGetSymbolAddress((void**)&xh_p,  g_xh);
    cudaGetSymbolAddress((void**)&wq_p,  g_wqkvh);
    cudaGetSymbolAddress((void**)&wp_p,  g_wprojh);

    cudaFuncSetAttribute(gemm_fp16<true>,
                         cudaFuncAttributeMaxDynamicSharedMemorySize, GEMM_SMEM);
    cudaFuncSetAttribute(gemm_fp16<false>,
                         cudaFuncAttributeMaxDynamicSharedMemorySize, GEMM_SMEM);
    cudaFuncSetAttribute(attn_tc,
                         cudaFuncAttributeMaxDynamicSharedMemorySize, ATTN_SMEM);

    // 0) operand prep: x -> half pair-perm8; weights -> transposed half pair-perm8
    cvt_x_h<<<(M_*C_/16)/256, 256>>>((const float4*)x, (__half2*)xh_p, M_*C_/16);
    {
        dim3 blk(32, 8);
        dim3 gq(NQKV_/32, C_/32);
        cvt_transpose_h<<<gq, blk>>>(Wqkv, wq_p, C_, NQKV_);
        dim3 gp(C_/32, C_/32);
        cvt_transpose_h<<<gp, blk>>>(Wproj, wp_p, C_, C_);
    }

    // 1) QKV GEMM (fp16 m16n8k16) -> fp32 element-perm8 qkv for attention
    dim3 g1(NQKV_/128, M_/128);
    gemm_fp16<true><<<g1, 128, GEMM_SMEM>>>(xh_p, wq_p, bqkv, qkv_p, M_, NQKV_, C_);

    // 2) Flash attention (tf32 internals) -> half pair-perm8 att
    dim3 g2(T_/128, B_*NH_);
    attn_tc<<<g2, 256, ATTN_SMEM>>>(qkv_p, att_p);

    // 3) Output projection (fp16) -> natural fp32 out
    dim3 g3(C_/128, M_/128);
    gemm_fp16<false><<<g3, 128, GEMM_SMEM>>>(att_p, wp_p, bproj, out, M_, C_, C_);
}

// round 14
// speedup vs baseline: 1.7025x; 1.3575x over previous
#include <cuda_runtime.h>
#include <cuda_fp16.h>
#include <cstdint>

// Problem constants
#define B_    2
#define T_    2048
#define C_    1024
#define NH_   16
#define HD_   64
#define M_    (B_ * T_)     // 4096
#define NQKV_ (3 * C_)      // 3072

// Scratch (device globals: allocation-free)
__device__ __half g_qkvh[(size_t)M_ * NQKV_];    // qkv (half, pair-perm8 along d)
__device__ __half g_vth[(size_t)B_ * C_ * T_];   // V^T [b][c'][t] (half, pair-perm8 t)
__device__ __half g_att[(size_t)M_ * C_];        // attention out (half, pair-perm8)
__device__ __half g_xh [(size_t)M_ * C_];        // x -> half, pair-perm8
__device__ __half g_wqkvh[(size_t)C_ * NQKV_];   // Wqkv^T -> half [N][K], pair-perm8
__device__ __half g_wprojh[(size_t)C_ * C_];     // Wproj^T -> half [N][K], pair-perm8

// ---------------------------------------------------------------------------
// helpers
// ---------------------------------------------------------------------------
__device__ __forceinline__ float ex2f(float x) {
    float y;
    asm volatile("ex2.approx.ftz.f32 %0, %1;" : "=f"(y) : "f"(x));
    return y;
}
__device__ __forceinline__ void cp16(uint32_t dsm, const void* src) {
    asm volatile("cp.async.ca.shared.global [%0], [%1], 16;" :: "r"(dsm), "l"(src));
}
#define CP_COMMIT() asm volatile("cp.async.commit_group;")
#define CP_WAIT0()  asm volatile("cp.async.wait_group 0;")

// within-8 permutation (forward map): true unit k -> storage position.
__device__ __host__ __forceinline__ int perm8(int k) { return ((k & 3) << 1) | (k >> 2); }

// fp16 warp mma: K=16 per instruction, fp32 accumulate
#define MMA_F16(d, a0,a1,a2,a3, b0,b1)                                    \
    asm volatile("mma.sync.aligned.m16n8k16.row.col.f32.f16.f16.f32 "     \
        "{%0,%1,%2,%3}, {%4,%5,%6,%7}, {%8,%9}, {%0,%1,%2,%3};"           \
        : "+f"((d)[0]), "+f"((d)[1]), "+f"((d)[2]), "+f"((d)[3])          \
        : "r"(a0), "r"(a1), "r"(a2), "r"(a3), "r"(b0), "r"(b1))

// ---------------------------------------------------------------------------
// cvt kernels: fp32 -> half with pair-perm8 within 16-half groups.
// ---------------------------------------------------------------------------
__global__ void cvt_x_h(const float4* __restrict__ in,
                        __half2* __restrict__ out, int n16) {
    int i = blockIdx.x * blockDim.x + threadIdx.x;
    if (i < n16) {
        float4 v0 = in[4*i], v1 = in[4*i+1], v2 = in[4*i+2], v3 = in[4*i+3];
        __half2* o = out + 8*i;
        o[0] = __floats2half2_rn(v0.x, v0.y);   // pair 0
        o[1] = __floats2half2_rn(v2.x, v2.y);   // pair 4
        o[2] = __floats2half2_rn(v0.z, v0.w);   // pair 1
        o[3] = __floats2half2_rn(v2.z, v2.w);   // pair 5
        o[4] = __floats2half2_rn(v1.x, v1.y);   // pair 2
        o[5] = __floats2half2_rn(v3.x, v3.y);   // pair 6
        o[6] = __floats2half2_rn(v1.z, v1.w);   // pair 3
        o[7] = __floats2half2_rn(v3.z, v3.w);   // pair 7
    }
}

// W [K][N] fp32 -> W' [N][K] half (pair-perm8 within 16-k groups)
__global__ void cvt_transpose_h(const float* __restrict__ in,
                                __half* __restrict__ out, int K, int N) {
    __shared__ float t[32][33];
    const int k0 = blockIdx.y * 32, n0 = blockIdx.x * 32;
    const int tx = threadIdx.x, ty = threadIdx.y;
#pragma unroll
    for (int i = 0; i < 4; i++)
        t[ty + 8*i][tx] = in[(size_t)(k0 + ty + 8*i) * N + n0 + tx];
    __syncthreads();
    const int kpos = (tx & ~15) | (perm8((tx >> 1) & 7) << 1) | (tx & 1);
#pragma unroll
    for (int i = 0; i < 4; i++) {
        int n = ty + 8*i;
        out[(size_t)(n0 + n) * K + k0 + kpos] = __float2half_rn(t[tx][n]);
    }
}

// V section of qkvh [r][c'] -> vt[b][c'][tpos] (half), pair-perm8 along t.
__global__ void vt_transpose(const __half* __restrict__ qkvh,
                             __half* __restrict__ vt) {
    __shared__ __half t[32][33];
    const int c0 = blockIdx.x * 32, r0 = blockIdx.y * 32;
    const int tx = threadIdx.x, ty = threadIdx.y;
#pragma unroll
    for (int i = 0; i < 4; i++)
        t[ty + 8*i][tx] = qkvh[(size_t)(r0 + ty + 8*i) * NQKV_ + 2*C_ + c0 + tx];
    __syncthreads();
    const int b = r0 >> 11;            // T_ = 2048
    const int tbase = r0 & (T_ - 1);
    const int v = tx & 15;
    const int tpos = (tx & ~15) | (perm8((v >> 1) & 7) << 1) | (v & 1);
#pragma unroll
    for (int i = 0; i < 4; i++) {
        int c = c0 + ty + 8*i;
        vt[((size_t)b * C_ + c) * T_ + tbase + tpos] = t[tx][ty + 8*i];
    }
}

// ---------------------------------------------------------------------------
// FP16 GEMM + bias.  C[M,N] = A[M,K] @ B'[N,K]^T + bias.
// 128 threads / 4 warps, warp tile 64x64, block 128x128x64(k halves),
// m16n8k16, 2-stage cp.async, single barrier per k-tile.
// PERM_OUT: HALF output, pair-perm8 positions (qkv/att format).
// ---------------------------------------------------------------------------
#define ST_H 80
#define STG_H (128 * ST_H)                  // halves per operand per stage
#define GEMM_SMEM (2 * 2 * STG_H * 2)       // 81920 B

template<bool PERM_OUT>
__global__ __launch_bounds__(128, 2)
void gemm_fp16(const __half* __restrict__ A, const __half* __restrict__ Bm,
               const float* __restrict__ bias, float* __restrict__ Cm,
               __half* __restrict__ Ch, int M, int N, int K) {
    extern __shared__ __half smh[];

    const int tid  = threadIdx.x;
    const int lane = tid & 31, warp = tid >> 5;
    const int wm = warp >> 1, wn = warp & 1;     // 2x2 warp grid, 64x64 tiles
    const int g  = lane >> 2, t4 = lane & 3;
    const int row0 = blockIdx.y * 128, col0 = blockIdx.x * 128;

    const uint32_t sbase = (uint32_t)__cvta_generic_to_shared(smh);

    auto issue = [&](int kt) {
        const int buf = kt & 1;
        const uint32_t sA = sbase + (uint32_t)(buf * 2 * STG_H) * 2;
        const uint32_t sB = sA + (uint32_t)STG_H * 2;
#pragma unroll
        for (int i = 0; i < 8; i++) {
            int idx = tid + 128 * i;
            int r = idx >> 3, s8 = idx & 7;
            cp16(sA + (uint32_t)(r * ST_H * 2 + s8 * 16),
                 &A[(size_t)(row0 + r) * K + kt * 64 + s8 * 8]);
        }
#pragma unroll
        for (int i = 0; i < 8; i++) {
            int idx = tid + 128 * i;
            int r = idx >> 3, s8 = idx & 7;
            cp16(sB + (uint32_t)(r * ST_H * 2 + s8 * 16),
                 &Bm[(size_t)(col0 + r) * K + kt * 64 + s8 * 8]);
        }
    };

    float acc[4][8][4];
#pragma unroll
    for (int mt = 0; mt < 4; mt++)
#pragma unroll
        for (int nt = 0; nt < 8; nt++)
#pragma unroll
            for (int c = 0; c < 4; c++) acc[mt][nt][c] = 0.f;

    const int KT = K >> 6;
    issue(0); CP_COMMIT();

    for (int kt = 0; kt < KT; kt++) {
        CP_WAIT0();
        __syncthreads();
        if (kt + 1 < KT) { issue(kt + 1); CP_COMMIT(); }

        const __half* Ab = smh + (kt & 1) * 2 * STG_H;
        const __half* Bb = Ab + STG_H;

#pragma unroll
        for (int kki = 0; kki < 4; kki++) {
            const int kk = kki * 16;
            uint2 ral[4], rah[4];
#pragma unroll
            for (int mt = 0; mt < 4; mt++) {
                const __half* ap = Ab + (wm*64 + mt*16 + g) * ST_H + kk + 4*t4;
                ral[mt] = *reinterpret_cast<const uint2*>(ap);
                rah[mt] = *reinterpret_cast<const uint2*>(ap + 8*ST_H);
            }
#pragma unroll
            for (int nt = 0; nt < 8; nt++) {
                uint2 rb = *reinterpret_cast<const uint2*>(
                    Bb + (wn*64 + nt*8 + g) * ST_H + kk + 4*t4);
#pragma unroll
                for (int mt = 0; mt < 4; mt++)
                    MMA_F16(acc[mt][nt], ral[mt].x, rah[mt].x,
                            ral[mt].y, rah[mt].y, rb.x, rb.y);
            }
        }
    }

    // epilogue: + bias (true columns)
#pragma unroll
    for (int mt = 0; mt < 4; mt++) {
        const int rA = row0 + wm*64 + mt*16 + g;
        const int rB = rA + 8;
#pragma unroll
        for (int nt = 0; nt < 8; nt++) {
            const int c = col0 + wn*64 + nt*8 + 2*t4;
            const float b0 = bias[c], b1 = bias[c + 1];
            float v0 = acc[mt][nt][0] + b0, v1 = acc[mt][nt][1] + b1;
            float v2 = acc[mt][nt][2] + b0, v3 = acc[mt][nt][3] + b1;
            if (PERM_OUT) {
                // true pair p=(nt&1)*4+t4 of 16-group -> unit (t4<<1)|(nt&1)
                const int hc = col0 + wn*64 + ((nt >> 1) << 4)
                             + ((((t4 << 1) | (nt & 1))) << 1);
                *reinterpret_cast<__half2*>(&Ch[(size_t)rA * N + hc]) =
                    __floats2half2_rn(v0, v1);
                *reinterpret_cast<__half2*>(&Ch[(size_t)rB * N + hc]) =
                    __floats2half2_rn(v2, v3);
            } else {
                *reinterpret_cast<float2*>(&Cm[(size_t)rA * N + c]) = make_float2(v0, v1);
                *reinterpret_cast<float2*>(&Cm[(size_t)rB * N + c]) = make_float2(v2, v3);
            }
        }
    }
}

// ---------------------------------------------------------------------------
// FP16 tensor-core flash attention.  BM=128, 256 threads, 8 warps x 16 rows.
// Q/K half pair-perm8 along d (from QKV GEMM); V^T half pair-perm8 along t.
// S and PV via m16n8k16; softmax fp32 exp2-domain (scale folded post-mma).
// O accumulates in V-position space == pair-perm8 att layout -> direct write.
// ---------------------------------------------------------------------------
#define AH 80
#define AKV_TILE (64 * AH + 64 * AH)          // halves: K + Vt per stage
#define ATTN_SMEM ((128*AH + 2*AKV_TILE + 128*AH) * 2)   // 81920 B

#define MASKVAL (-6e30f)
#define MINIT   (-1e30f)

__global__ __launch_bounds__(256, 1)
void attn_fp16(const __half* __restrict__ qkvh, const __half* __restrict__ vth,
               __half* __restrict__ att) {
    extern __shared__ __half smh[];
    __half* Qs  = smh;                       // [128][AH]
    __half* KV0 = Qs + 128*AH;               // 2 stages: K[64][AH] + Vt[64][AH]
    __half* Ps  = KV0 + 2*AKV_TILE;          // [128][AH]

    const int tid  = threadIdx.x;
    const int lane = tid & 31, warp = tid >> 5;
    const int g = lane >> 2, t4 = lane & 3;
    const int qb = gridDim.x - 1 - blockIdx.x;   // heavy tiles first
    const int bh = blockIdx.y;
    const int b = bh >> 4, h = bh & 15;
    const int m0 = qb * 128;
    const int rb = warp * 16;

    const __half* qbase = qkvh + ((size_t)b*T_ + m0)*NQKV_ + h*HD_;
    const __half* kbase = qkvh + (size_t)b*T_*NQKV_ + h*HD_ + C_;
    const __half* vtb   = vth + ((size_t)b*C_ + h*HD_) * T_;

    const uint32_t sq  = (uint32_t)__cvta_generic_to_shared(Qs);
    const uint32_t skv = (uint32_t)__cvta_generic_to_shared(KV0);

    auto issue = [&](int kvb) {
        const uint32_t sK = skv + (uint32_t)((kvb & 1) * AKV_TILE) * 2;
        const uint32_t sV = sK + (uint32_t)(64 * AH) * 2;
        const int jb = kvb * 64;
#pragma unroll
        for (int i = 0; i < 2; i++) {
            int idx = tid + 256 * i;
            int j = idx >> 3, s8 = idx & 7;
            cp16(sK + (uint32_t)(j*AH + s8*8) * 2,
                 &kbase[(size_t)(jb + j)*NQKV_ + s8*8]);
        }
#pragma unroll
        for (int i = 0; i < 2; i++) {
            int idx = tid + 256 * i;
            int d = idx >> 3, s8 = idx & 7;
            cp16(sV + (uint32_t)(d*AH + s8*8) * 2,
                 &vtb[(size_t)d * T_ + jb + s8*8]);
        }
    };

    // Q tile (raw; softmax scale folded post-mma)
#pragma unroll
    for (int i = 0; i < 4; i++) {
        int idx = tid + 256 * i;
        int r = idx >> 3, s8 = idx & 7;
        cp16(sq + (uint32_t)(r*AH + s8*8) * 2, &qbase[(size_t)r*NQKV_ + s8*8]);
    }
    issue(0); CP_COMMIT();

    float o[8][4];
    float mrow[2] = {MINIT, MINIT}, lrow[2] = {0.f, 0.f};
#pragma unroll
    for (int nt = 0; nt < 8; nt++)
#pragma unroll
        for (int c = 0; c < 4; c++) o[nt][c] = 0.f;

    const float SC = 0.125f * 1.44269504088896340736f;   // 1/sqrt(64)*log2(e)
    const int nkv = 2*qb + 2;
    for (int kvb = 0; kvb < nkv; kvb++) {
        const int jb = kvb * 64;
        CP_WAIT0();
        __syncthreads();
        if (kvb + 1 < nkv) { issue(kvb + 1); CP_COMMIT(); }

        const __half* Ks = KV0 + (kvb & 1) * AKV_TILE;
        const __half* Vs = Ks + 64 * AH;

        if (jb > m0 + rb + 15) continue;

        // ---- S = Q @ K^T (both pair-perm8 along d: invariant) ----
        float s[8][4];
#pragma unroll
        for (int nt = 0; nt < 8; nt++)
#pragma unroll
            for (int c = 0; c < 4; c++) s[nt][c] = 0.f;

#pragma unroll
        for (int kk = 0; kk < 64; kk += 16) {
            const __half* ap = Qs + (rb + g)*AH + kk + 4*t4;
            uint2 qa0 = *reinterpret_cast<const uint2*>(ap);
            uint2 qa1 = *reinterpret_cast<const uint2*>(ap + 8*AH);
#pragma unroll
            for (int nt = 0; nt < 8; nt++) {
                uint2 kf = *reinterpret_cast<const uint2*>(
                    Ks + (nt*8 + g)*AH + kk + 4*t4);
                MMA_F16(s[nt], qa0.x, qa1.x, qa0.y, qa1.y, kf.x, kf.y);
            }
        }

        // ---- scale, causal mask (true j coords; K rows natural) ----
#pragma unroll
        for (int nt = 0; nt < 8; nt++)
#pragma unroll
            for (int c = 0; c < 4; c++) s[nt][c] *= SC;
        if (jb + 63 > m0 + rb) {
            const int r0 = m0 + rb + g, r1 = r0 + 8;
#pragma unroll
            for (int nt = 0; nt < 8; nt++) {
                int cb = jb + nt*8 + 2*t4;
                if (cb     > r0) s[nt][0] = MASKVAL;
                if (cb + 1 > r0) s[nt][1] = MASKVAL;
                if (cb     > r1) s[nt][2] = MASKVAL;
                if (cb + 1 > r1) s[nt][3] = MASKVAL;
            }
        }

        // ---- online softmax (exp2 domain) ----
        float mx0 = MINIT, mx1 = MINIT;
#pragma unroll
        for (int nt = 0; nt < 8; nt++) {
            mx0 = fmaxf(mx0, fmaxf(s[nt][0], s[nt][1]));
            mx1 = fmaxf(mx1, fmaxf(s[nt][2], s[nt][3]));
        }
        mx0 = fmaxf(mx0, __shfl_xor_sync(0xffffffffu, mx0, 1));
        mx0 = fmaxf(mx0, __shfl_xor_sync(0xffffffffu, mx0, 2));
        mx1 = fmaxf(mx1, __shfl_xor_sync(0xffffffffu, mx1, 1));
        mx1 = fmaxf(mx1, __shfl_xor_sync(0xffffffffu, mx1, 2));
        const float mn0 = fmaxf(mrow[0], mx0), mn1 = fmaxf(mrow[1], mx1);
        const float al0 = ex2f(mrow[0] - mn0), al1 = ex2f(mrow[1] - mn1);
        mrow[0] = mn0; mrow[1] = mn1;

        float ls0 = 0.f, ls1 = 0.f;
        __half* p0 = Ps + (rb + g)*AH;
        __half* p1 = Ps + (rb + g + 8)*AH;
#pragma unroll
        for (int nt = 0; nt < 8; nt++) {
            s[nt][0] = ex2f(s[nt][0] - mn0);
            s[nt][1] = ex2f(s[nt][1] - mn0);
            s[nt][2] = ex2f(s[nt][2] - mn1);
            s[nt][3] = ex2f(s[nt][3] - mn1);
            ls0 += s[nt][0] + s[nt][1];
            ls1 += s[nt][2] + s[nt][3];
            o[nt][0] *= al0; o[nt][1] *= al0;
            o[nt][2] *= al1; o[nt][3] *= al1;
            // stage P half, pair-perm8 along j: pair p=(nt&1)*4+t4 ->
            // unit (t4<<1)|(nt&1) of group nt>>1
            const int hoff = ((nt >> 1) << 4) + ((((t4 << 1) | (nt & 1))) << 1);
            *reinterpret_cast<__half2*>(p0 + hoff) = __floats2half2_rn(s[nt][0], s[nt][1]);
            *reinterpret_cast<__half2*>(p1 + hoff) = __floats2half2_rn(s[nt][2], s[nt][3]);
        }
        ls0 += __shfl_xor_sync(0xffffffffu, ls0, 1);
        ls0 += __shfl_xor_sync(0xffffffffu, ls0, 2);
        ls1 += __shfl_xor_sync(0xffffffffu, ls1, 1);
        ls1 += __shfl_xor_sync(0xffffffffu, ls1, 2);
        lrow[0] = lrow[0]*al0 + ls0;
        lrow[1] = lrow[1]*al1 + ls1;

        __syncwarp();

        // ---- O += P @ V^T (both pair-perm8 along j: invariant) ----
#pragma unroll
        for (int kk = 0; kk < 64; kk += 16) {
            const __half* ap = Ps + (rb + g)*AH + kk + 4*t4;
            uint2 pa0 = *reinterpret_cast<const uint2*>(ap);
            uint2 pa1 = *reinterpret_cast<const uint2*>(ap + 8*AH);
#pragma unroll
            for (int nt = 0; nt < 8; nt++) {
                uint2 vf = *reinterpret_cast<const uint2*>(
                    Vs + (nt*8 + g)*AH + kk + 4*t4);
                MMA_F16(o[nt], pa0.x, pa1.x, pa0.y, pa1.y, vf.x, vf.y);
            }
        }
    }

    // ---- epilogue: O columns are V^T-row positions == att layout ----
    const float inv0 = 1.0f / lrow[0], inv1 = 1.0f / lrow[1];
    const size_t r0 = (size_t)b*T_ + m0 + rb + g;
    const size_t r1 = r0 + 8;
#pragma unroll
    for (int nt = 0; nt < 8; nt++) {
        const int hc = h*HD_ + nt*8 + 2*t4;
        *reinterpret_cast<__half2*>(&att[r0*C_ + hc]) =
            __floats2half2_rn(o[nt][0] * inv0, o[nt][1] * inv0);
        *reinterpret_cast<__half2*>(&att[r1*C_ + hc]) =
            __floats2half2_rn(o[nt][2] * inv1, o[nt][3] * inv1);
    }
}

// ---------------------------------------------------------------------------
// Launch
// ---------------------------------------------------------------------------
extern "C" void kernel_launch(void* const* d_in, const int* in_sizes, int n_in,
                              void* d_out, int out_size) {
    const float* x     = (const float*)d_in[0];
    const float* Wqkv  = (const float*)d_in[1];
    const float* bqkv  = (const float*)d_in[2];
    const float* Wproj = (const float*)d_in[3];
    const float* bproj = (const float*)d_in[4];
    float* out = (float*)d_out;

    __half *qkvh_p, *vth_p, *att_p, *xh_p, *wq_p, *wp_p;
    cudaGetSymbolAddress((void**)&qkvh_p, g_qkvh);
    cudaGetSymbolAddress((void**)&vth_p,  g_vth);
    cudaGetSymbolAddress((void**)&att_p,  g_att);
    cudaGetSymbolAddress((void**)&xh_p,   g_xh);
    cudaGetSymbolAddress((void**)&wq_p,   g_wqkvh);
    cudaGetSymbolAddress((void**)&wp_p,   g_wprojh);

    cudaFuncSetAttribute(gemm_fp16<true>,
                         cudaFuncAttributeMaxDynamicSharedMemorySize, GEMM_SMEM);
    cudaFuncSetAttribute(gemm_fp16<false>,
                         cudaFuncAttributeMaxDynamicSharedMemorySize, GEMM_SMEM);
    cudaFuncSetAttribute(attn_fp16,
                         cudaFuncAttributeMaxDynamicSharedMemorySize, ATTN_SMEM);

    // 0) operand prep
    cvt_x_h<<<(M_*C_/16)/256, 256>>>((const float4*)x, (__half2*)xh_p, M_*C_/16);
    {
        dim3 blk(32, 8);
        dim3 gq(NQKV_/32, C_/32);
        cvt_transpose_h<<<gq, blk>>>(Wqkv, wq_p, C_, NQKV_);
        dim3 gp(C_/32, C_/32);
        cvt_transpose_h<<<gp, blk>>>(Wproj, wp_p, C_, C_);
    }

    // 1) QKV GEMM (fp16) -> half pair-perm8 qkv
    dim3 g1(NQKV_/128, M_/128);
    gemm_fp16<true><<<g1, 128, GEMM_SMEM>>>(xh_p, wq_p, bqkv, nullptr, qkvh_p,
                                            M_, NQKV_, C_);

    // 1b) V^T (pair-perm8 along t)
    {
        dim3 blk(32, 8);
        dim3 gv(C_/32, M_/32);
        vt_transpose<<<gv, blk>>>(qkvh_p, vth_p);
    }

    // 2) FP16 flash attention -> half pair-perm8 att
    dim3 g2(T_/128, B_*NH_);
    attn_fp16<<<g2, 256, ATTN_SMEM>>>(qkvh_p, vth_p, att_p);

    // 3) Output projection (fp16) -> natural fp32 out
    dim3 g3(C_/128, M_/128);
    gemm_fp16<false><<<g3, 128, GEMM_SMEM>>>(att_p, wp_p, bproj, out, nullptr,
                                             M_, C_, C_);
}

// round 15
// speedup vs baseline: 1.7156x; 1.0077x over previous
#include <cuda_runtime.h>
#include <cuda_fp16.h>
#include <cstdint>

// Problem constants
#define B_    2
#define T_    2048
#define C_    1024
#define NH_   16
#define HD_   64
#define M_    (B_ * T_)     // 4096
#define NQKV_ (3 * C_)      // 3072

// Scratch (device globals: allocation-free)
__device__ __half g_qkvh[(size_t)M_ * NQKV_];    // qkv (half, pair-perm8 along d)
__device__ __half g_vth[(size_t)B_ * C_ * T_];   // V^T [b][c'][t] (half, pair-perm8 t)
__device__ __half g_att[(size_t)M_ * C_];        // attention out (half, pair-perm8)
__device__ __half g_xh [(size_t)M_ * C_];        // x -> half, pair-perm8
__device__ __half g_wqkvh[(size_t)C_ * NQKV_];   // Wqkv^T -> half [N][K], pair-perm8
__device__ __half g_wprojh[(size_t)C_ * C_];     // Wproj^T -> half [N][K], pair-perm8

// ---------------------------------------------------------------------------
// helpers
// ---------------------------------------------------------------------------
__device__ __forceinline__ float ex2f(float x) {
    float y;
    asm volatile("ex2.approx.ftz.f32 %0, %1;" : "=f"(y) : "f"(x));
    return y;
}
__device__ __forceinline__ void cp16(uint32_t dsm, const void* src) {
    asm volatile("cp.async.ca.shared.global [%0], [%1], 16;" :: "r"(dsm), "l"(src));
}
#define CP_COMMIT() asm volatile("cp.async.commit_group;")
#define CP_WAIT0()  asm volatile("cp.async.wait_group 0;")

// within-8 permutation (forward map): true unit k -> storage position.
__device__ __host__ __forceinline__ int perm8(int k) { return ((k & 3) << 1) | (k >> 2); }

// fp16 warp mma: K=16 per instruction, fp32 accumulate
#define MMA_F16(d, a0,a1,a2,a3, b0,b1)                                    \
    asm volatile("mma.sync.aligned.m16n8k16.row.col.f32.f16.f16.f32 "     \
        "{%0,%1,%2,%3}, {%4,%5,%6,%7}, {%8,%9}, {%0,%1,%2,%3};"           \
        : "+f"((d)[0]), "+f"((d)[1]), "+f"((d)[2]), "+f"((d)[3])          \
        : "r"(a0), "r"(a1), "r"(a2), "r"(a3), "r"(b0), "r"(b1))

// ---------------------------------------------------------------------------
// cvt kernels: fp32 -> half with pair-perm8 within 16-half groups.
// ---------------------------------------------------------------------------
__global__ void cvt_x_h(const float4* __restrict__ in,
                        __half2* __restrict__ out, int n16) {
    int i = blockIdx.x * blockDim.x + threadIdx.x;
    if (i < n16) {
        float4 v0 = in[4*i], v1 = in[4*i+1], v2 = in[4*i+2], v3 = in[4*i+3];
        __half2* o = out + 8*i;
        o[0] = __floats2half2_rn(v0.x, v0.y);   // pair 0
        o[1] = __floats2half2_rn(v2.x, v2.y);   // pair 4
        o[2] = __floats2half2_rn(v0.z, v0.w);   // pair 1
        o[3] = __floats2half2_rn(v2.z, v2.w);   // pair 5
        o[4] = __floats2half2_rn(v1.x, v1.y);   // pair 2
        o[5] = __floats2half2_rn(v3.x, v3.y);   // pair 6
        o[6] = __floats2half2_rn(v1.z, v1.w);   // pair 3
        o[7] = __floats2half2_rn(v3.z, v3.w);   // pair 7
    }
}

// W [K][N] fp32 -> W' [N][K] half (pair-perm8 within 16-k groups)
__global__ void cvt_transpose_h(const float* __restrict__ in,
                                __half* __restrict__ out, int K, int N) {
    __shared__ float t[32][33];
    const int k0 = blockIdx.y * 32, n0 = blockIdx.x * 32;
    const int tx = threadIdx.x, ty = threadIdx.y;
#pragma unroll
    for (int i = 0; i < 4; i++)
        t[ty + 8*i][tx] = in[(size_t)(k0 + ty + 8*i) * N + n0 + tx];
    __syncthreads();
    const int kpos = (tx & ~15) | (perm8((tx >> 1) & 7) << 1) | (tx & 1);
#pragma unroll
    for (int i = 0; i < 4; i++) {
        int n = ty + 8*i;
        out[(size_t)(n0 + n) * K + k0 + kpos] = __float2half_rn(t[tx][n]);
    }
}

// V section of qkvh [r][c'] -> vt[b][c'][tpos] (half), pair-perm8 along t.
__global__ void vt_transpose(const __half* __restrict__ qkvh,
                             __half* __restrict__ vt) {
    __shared__ __half t[32][33];
    const int c0 = blockIdx.x * 32, r0 = blockIdx.y * 32;
    const int tx = threadIdx.x, ty = threadIdx.y;
#pragma unroll
    for (int i = 0; i < 4; i++)
        t[ty + 8*i][tx] = qkvh[(size_t)(r0 + ty + 8*i) * NQKV_ + 2*C_ + c0 + tx];
    __syncthreads();
    const int b = r0 >> 11;            // T_ = 2048
    const int tbase = r0 & (T_ - 1);
    const int v = tx & 15;
    const int tpos = (tx & ~15) | (perm8((v >> 1) & 7) << 1) | (v & 1);
#pragma unroll
    for (int i = 0; i < 4; i++) {
        int c = c0 + ty + 8*i;
        vt[((size_t)b * C_ + c) * T_ + tbase + tpos] = t[tx][ty + 8*i];
    }
}

// ---------------------------------------------------------------------------
// FP16 GEMM + bias.  C[M,N] = A[M,K] @ B'[N,K]^T + bias.
// 128 threads / 4 warps, warp tile 64x64, block 128x128x64(k halves),
// m16n8k16, 2-stage cp.async, single barrier per k-tile.
// PERM_OUT: HALF output, pair-perm8 positions (qkv/att format).
// ---------------------------------------------------------------------------
#define ST_H 80
#define STG_H (128 * ST_H)                  // halves per operand per stage
#define GEMM_SMEM (2 * 2 * STG_H * 2)       // 81920 B

template<bool PERM_OUT>
__global__ __launch_bounds__(128, 2)
void gemm_fp16(const __half* __restrict__ A, const __half* __restrict__ Bm,
               const float* __restrict__ bias, float* __restrict__ Cm,
               __half* __restrict__ Ch, int M, int N, int K) {
    extern __shared__ __half smh[];

    const int tid  = threadIdx.x;
    const int lane = tid & 31, warp = tid >> 5;
    const int wm = warp >> 1, wn = warp & 1;     // 2x2 warp grid, 64x64 tiles
    const int g  = lane >> 2, t4 = lane & 3;
    const int row0 = blockIdx.y * 128, col0 = blockIdx.x * 128;

    const uint32_t sbase = (uint32_t)__cvta_generic_to_shared(smh);

    auto issue = [&](int kt) {
        const int buf = kt & 1;
        const uint32_t sA = sbase + (uint32_t)(buf * 2 * STG_H) * 2;
        const uint32_t sB = sA + (uint32_t)STG_H * 2;
#pragma unroll
        for (int i = 0; i < 8; i++) {
            int idx = tid + 128 * i;
            int r = idx >> 3, s8 = idx & 7;
            cp16(sA + (uint32_t)(r * ST_H * 2 + s8 * 16),
                 &A[(size_t)(row0 + r) * K + kt * 64 + s8 * 8]);
        }
#pragma unroll
        for (int i = 0; i < 8; i++) {
            int idx = tid + 128 * i;
            int r = idx >> 3, s8 = idx & 7;
            cp16(sB + (uint32_t)(r * ST_H * 2 + s8 * 16),
                 &Bm[(size_t)(col0 + r) * K + kt * 64 + s8 * 8]);
        }
    };

    float acc[4][8][4];
#pragma unroll
    for (int mt = 0; mt < 4; mt++)
#pragma unroll
        for (int nt = 0; nt < 8; nt++)
#pragma unroll
            for (int c = 0; c < 4; c++) acc[mt][nt][c] = 0.f;

    const int KT = K >> 6;
    issue(0); CP_COMMIT();

    for (int kt = 0; kt < KT; kt++) {
        CP_WAIT0();
        __syncthreads();
        if (kt + 1 < KT) { issue(kt + 1); CP_COMMIT(); }

        const __half* Ab = smh + (kt & 1) * 2 * STG_H;
        const __half* Bb = Ab + STG_H;

#pragma unroll
        for (int kki = 0; kki < 4; kki++) {
            const int kk = kki * 16;
            uint2 ral[4], rah[4];
#pragma unroll
            for (int mt = 0; mt < 4; mt++) {
                const __half* ap = Ab + (wm*64 + mt*16 + g) * ST_H + kk + 4*t4;
                ral[mt] = *reinterpret_cast<const uint2*>(ap);
                rah[mt] = *reinterpret_cast<const uint2*>(ap + 8*ST_H);
            }
#pragma unroll
            for (int nt = 0; nt < 8; nt++) {
                uint2 rb = *reinterpret_cast<const uint2*>(
                    Bb + (wn*64 + nt*8 + g) * ST_H + kk + 4*t4);
#pragma unroll
                for (int mt = 0; mt < 4; mt++)
                    MMA_F16(acc[mt][nt], ral[mt].x, rah[mt].x,
                            ral[mt].y, rah[mt].y, rb.x, rb.y);
            }
        }
    }

    // epilogue: + bias (true columns)
#pragma unroll
    for (int mt = 0; mt < 4; mt++) {
        const int rA = row0 + wm*64 + mt*16 + g;
        const int rB = rA + 8;
#pragma unroll
        for (int nt = 0; nt < 8; nt++) {
            const int c = col0 + wn*64 + nt*8 + 2*t4;
            const float b0 = bias[c], b1 = bias[c + 1];
            float v0 = acc[mt][nt][0] + b0, v1 = acc[mt][nt][1] + b1;
            float v2 = acc[mt][nt][2] + b0, v3 = acc[mt][nt][3] + b1;
            if (PERM_OUT) {
                // true pair p=(nt&1)*4+t4 of 16-group -> unit (t4<<1)|(nt&1)
                const int hc = col0 + wn*64 + ((nt >> 1) << 4)
                             + ((((t4 << 1) | (nt & 1))) << 1);
                *reinterpret_cast<__half2*>(&Ch[(size_t)rA * N + hc]) =
                    __floats2half2_rn(v0, v1);
                *reinterpret_cast<__half2*>(&Ch[(size_t)rB * N + hc]) =
                    __floats2half2_rn(v2, v3);
            } else {
                *reinterpret_cast<float2*>(&Cm[(size_t)rA * N + c]) = make_float2(v0, v1);
                *reinterpret_cast<float2*>(&Cm[(size_t)rB * N + c]) = make_float2(v2, v3);
            }
        }
    }
}

// ---------------------------------------------------------------------------
// FP16 tensor-core flash attention.  BM=128, 256 threads, 8 warps x 16 rows.
// Q/K half pair-perm8 along d (from QKV GEMM); V^T half pair-perm8 along t.
// S and PV via m16n8k16; softmax fp32 exp2-domain (scale folded post-mma).
// O accumulates in V-position space == pair-perm8 att layout -> direct write.
// __launch_bounds__(256, 2): cap 128 regs -> 2 CTA/SM (82KB smem x2 fits).
// ---------------------------------------------------------------------------
#define AH 80
#define AKV_TILE (64 * AH + 64 * AH)          // halves: K + Vt per stage
#define ATTN_SMEM ((128*AH + 2*AKV_TILE + 128*AH) * 2)   // 81920 B

#define MASKVAL (-6e30f)
#define MINIT   (-1e30f)

__global__ __launch_bounds__(256, 2)
void attn_fp16(const __half* __restrict__ qkvh, const __half* __restrict__ vth,
               __half* __restrict__ att) {
    extern __shared__ __half smh[];
    __half* Qs  = smh;                       // [128][AH]
    __half* KV0 = Qs + 128*AH;               // 2 stages: K[64][AH] + Vt[64][AH]
    __half* Ps  = KV0 + 2*AKV_TILE;          // [128][AH]

    const int tid  = threadIdx.x;
    const int lane = tid & 31, warp = tid >> 5;
    const int g = lane >> 2, t4 = lane & 3;
    const int qb = gridDim.x - 1 - blockIdx.x;   // heavy tiles first
    const int bh = blockIdx.y;
    const int b = bh >> 4, h = bh & 15;
    const int m0 = qb * 128;
    const int rb = warp * 16;

    const __half* qbase = qkvh + ((size_t)b*T_ + m0)*NQKV_ + h*HD_;
    const __half* kbase = qkvh + (size_t)b*T_*NQKV_ + h*HD_ + C_;
    const __half* vtb   = vth + ((size_t)b*C_ + h*HD_) * T_;

    const uint32_t sq  = (uint32_t)__cvta_generic_to_shared(Qs);
    const uint32_t skv = (uint32_t)__cvta_generic_to_shared(KV0);

    auto issue = [&](int kvb) {
        const uint32_t sK = skv + (uint32_t)((kvb & 1) * AKV_TILE) * 2;
        const uint32_t sV = sK + (uint32_t)(64 * AH) * 2;
        const int jb = kvb * 64;
#pragma unroll
        for (int i = 0; i < 2; i++) {
            int idx = tid + 256 * i;
            int j = idx >> 3, s8 = idx & 7;
            cp16(sK + (uint32_t)(j*AH + s8*8) * 2,
                 &kbase[(size_t)(jb + j)*NQKV_ + s8*8]);
        }
#pragma unroll
        for (int i = 0; i < 2; i++) {
            int idx = tid + 256 * i;
            int d = idx >> 3, s8 = idx & 7;
            cp16(sV + (uint32_t)(d*AH + s8*8) * 2,
                 &vtb[(size_t)d * T_ + jb + s8*8]);
        }
    };

    // Q tile (raw; softmax scale folded post-mma)
#pragma unroll
    for (int i = 0; i < 4; i++) {
        int idx = tid + 256 * i;
        int r = idx >> 3, s8 = idx & 7;
        cp16(sq + (uint32_t)(r*AH + s8*8) * 2, &qbase[(size_t)r*NQKV_ + s8*8]);
    }
    issue(0); CP_COMMIT();

    float o[8][4];
    float mrow[2] = {MINIT, MINIT}, lrow[2] = {0.f, 0.f};
#pragma unroll
    for (int nt = 0; nt < 8; nt++)
#pragma unroll
        for (int c = 0; c < 4; c++) o[nt][c] = 0.f;

    const float SC = 0.125f * 1.44269504088896340736f;   // 1/sqrt(64)*log2(e)
    const int nkv = 2*qb + 2;
    for (int kvb = 0; kvb < nkv; kvb++) {
        const int jb = kvb * 64;
        CP_WAIT0();
        __syncthreads();
        if (kvb + 1 < nkv) { issue(kvb + 1); CP_COMMIT(); }

        const __half* Ks = KV0 + (kvb & 1) * AKV_TILE;
        const __half* Vs = Ks + 64 * AH;

        if (jb > m0 + rb + 15) continue;

        // ---- S = Q @ K^T (both pair-perm8 along d: invariant) ----
        float s[8][4];
#pragma unroll
        for (int nt = 0; nt < 8; nt++)
#pragma unroll
            for (int c = 0; c < 4; c++) s[nt][c] = 0.f;

#pragma unroll
        for (int kk = 0; kk < 64; kk += 16) {
            const __half* ap = Qs + (rb + g)*AH + kk + 4*t4;
            uint2 qa0 = *reinterpret_cast<const uint2*>(ap);
            uint2 qa1 = *reinterpret_cast<const uint2*>(ap + 8*AH);
#pragma unroll
            for (int nt = 0; nt < 8; nt++) {
                uint2 kf = *reinterpret_cast<const uint2*>(
                    Ks + (nt*8 + g)*AH + kk + 4*t4);
                MMA_F16(s[nt], qa0.x, qa1.x, qa0.y, qa1.y, kf.x, kf.y);
            }
        }

        // ---- scale, causal mask (true j coords; K rows natural) ----
#pragma unroll
        for (int nt = 0; nt < 8; nt++)
#pragma unroll
            for (int c = 0; c < 4; c++) s[nt][c] *= SC;
        if (jb + 63 > m0 + rb) {
            const int r0 = m0 + rb + g, r1 = r0 + 8;
#pragma unroll
            for (int nt = 0; nt < 8; nt++) {
                int cb = jb + nt*8 + 2*t4;
                if (cb     > r0) s[nt][0] = MASKVAL;
                if (cb + 1 > r0) s[nt][1] = MASKVAL;
                if (cb     > r1) s[nt][2] = MASKVAL;
                if (cb + 1 > r1) s[nt][3] = MASKVAL;
            }
        }

        // ---- online softmax (exp2 domain) ----
        float mx0 = MINIT, mx1 = MINIT;
#pragma unroll
        for (int nt = 0; nt < 8; nt++) {
            mx0 = fmaxf(mx0, fmaxf(s[nt][0], s[nt][1]));
            mx1 = fmaxf(mx1, fmaxf(s[nt][2], s[nt][3]));
        }
        mx0 = fmaxf(mx0, __shfl_xor_sync(0xffffffffu, mx0, 1));
        mx0 = fmaxf(mx0, __shfl_xor_sync(0xffffffffu, mx0, 2));
        mx1 = fmaxf(mx1, __shfl_xor_sync(0xffffffffu, mx1, 1));
        mx1 = fmaxf(mx1, __shfl_xor_sync(0xffffffffu, mx1, 2));
        const float mn0 = fmaxf(mrow[0], mx0), mn1 = fmaxf(mrow[1], mx1);
        const float al0 = ex2f(mrow[0] - mn0), al1 = ex2f(mrow[1] - mn1);
        mrow[0] = mn0; mrow[1] = mn1;

        float ls0 = 0.f, ls1 = 0.f;
        __half* p0 = Ps + (rb + g)*AH;
        __half* p1 = Ps + (rb + g + 8)*AH;
#pragma unroll
        for (int nt = 0; nt < 8; nt++) {
            s[nt][0] = ex2f(s[nt][0] - mn0);
            s[nt][1] = ex2f(s[nt][1] - mn0);
            s[nt][2] = ex2f(s[nt][2] - mn1);
            s[nt][3] = ex2f(s[nt][3] - mn1);
            ls0 += s[nt][0] + s[nt][1];
            ls1 += s[nt][2] + s[nt][3];
            o[nt][0] *= al0; o[nt][1] *= al0;
            o[nt][2] *= al1; o[nt][3] *= al1;
            // stage P half, pair-perm8 along j: pair p=(nt&1)*4+t4 ->
            // unit (t4<<1)|(nt&1) of group nt>>1
            const int hoff = ((nt >> 1) << 4) + ((((t4 << 1) | (nt & 1))) << 1);
            *reinterpret_cast<__half2*>(p0 + hoff) = __floats2half2_rn(s[nt][0], s[nt][1]);
            *reinterpret_cast<__half2*>(p1 + hoff) = __floats2half2_rn(s[nt][2], s[nt][3]);
        }
        ls0 += __shfl_xor_sync(0xffffffffu, ls0, 1);
        ls0 += __shfl_xor_sync(0xffffffffu, ls0, 2);
        ls1 += __shfl_xor_sync(0xffffffffu, ls1, 1);
        ls1 += __shfl_xor_sync(0xffffffffu, ls1, 2);
        lrow[0] = lrow[0]*al0 + ls0;
        lrow[1] = lrow[1]*al1 + ls1;

        __syncwarp();

        // ---- O += P @ V^T (both pair-perm8 along j: invariant) ----
#pragma unroll
        for (int kk = 0; kk < 64; kk += 16) {
            const __half* ap = Ps + (rb + g)*AH + kk + 4*t4;
            uint2 pa0 = *reinterpret_cast<const uint2*>(ap);
            uint2 pa1 = *reinterpret_cast<const uint2*>(ap + 8*AH);
#pragma unroll
            for (int nt = 0; nt < 8; nt++) {
                uint2 vf = *reinterpret_cast<const uint2*>(
                    Vs + (nt*8 + g)*AH + kk + 4*t4);
                MMA_F16(o[nt], pa0.x, pa1.x, pa0.y, pa1.y, vf.x, vf.y);
            }
        }
    }

    // ---- epilogue: O columns are V^T-row positions == att layout ----
    const float inv0 = 1.0f / lrow[0], inv1 = 1.0f / lrow[1];
    const size_t r0 = (size_t)b*T_ + m0 + rb + g;
    const size_t r1 = r0 + 8;
#pragma unroll
    for (int nt = 0; nt < 8; nt++) {
        const int hc = h*HD_ + nt*8 + 2*t4;
        *reinterpret_cast<__half2*>(&att[r0*C_ + hc]) =
            __floats2half2_rn(o[nt][0] * inv0, o[nt][1] * inv0);
        *reinterpret_cast<__half2*>(&att[r1*C_ + hc]) =
            __floats2half2_rn(o[nt][2] * inv1, o[nt][3] * inv1);
    }
}

// ---------------------------------------------------------------------------
// Launch
// ---------------------------------------------------------------------------
extern "C" void kernel_launch(void* const* d_in, const int* in_sizes, int n_in,
                              void* d_out, int out_size) {
    const float* x     = (const float*)d_in[0];
    const float* Wqkv  = (const float*)d_in[1];
    const float* bqkv  = (const float*)d_in[2];
    const float* Wproj = (const float*)d_in[3];
    const float* bproj = (const float*)d_in[4];
    float* out = (float*)d_out;

    __half *qkvh_p, *vth_p, *att_p, *xh_p, *wq_p, *wp_p;
    cudaGetSymbolAddress((void**)&qkvh_p, g_qkvh);
    cudaGetSymbolAddress((void**)&vth_p,  g_vth);
    cudaGetSymbolAddress((void**)&att_p,  g_att);
    cudaGetSymbolAddress((void**)&xh_p,   g_xh);
    cudaGetSymbolAddress((void**)&wq_p,   g_wqkvh);
    cudaGetSymbolAddress((void**)&wp_p,   g_wprojh);

    cudaFuncSetAttribute(gemm_fp16<true>,
                         cudaFuncAttributeMaxDynamicSharedMemorySize, GEMM_SMEM);
    cudaFuncSetAttribute(gemm_fp16<false>,
                         cudaFuncAttributeMaxDynamicSharedMemorySize, GEMM_SMEM);
    cudaFuncSetAttribute(attn_fp16,
                         cudaFuncAttributeMaxDynamicSharedMemorySize, ATTN_SMEM);

    // 0) operand prep
    cvt_x_h<<<(M_*C_/16)/256, 256>>>((const float4*)x, (__half2*)xh_p, M_*C_/16);
    {
        dim3 blk(32, 8);
        dim3 gq(NQKV_/32, C_/32);
        cvt_transpose_h<<<gq, blk>>>(Wqkv, wq_p, C_, NQKV_);
        dim3 gp(C_/32, C_/32);
        cvt_transpose_h<<<gp, blk>>>(Wproj, wp_p, C_, C_);
    }

    // 1) QKV GEMM (fp16) -> half pair-perm8 qkv
    dim3 g1(NQKV_/128, M_/128);
    gemm_fp16<true><<<g1, 128, GEMM_SMEM>>>(xh_p, wq_p, bqkv, nullptr, qkvh_p,
                                            M_, NQKV_, C_);

    // 1b) V^T (pair-perm8 along t)
    {
        dim3 blk(32, 8);
        dim3 gv(C_/32, M_/32);
        vt_transpose<<<gv, blk>>>(qkvh_p, vth_p);
    }

    // 2) FP16 flash attention (2 CTA/SM) -> half pair-perm8 att
    dim3 g2(T_/128, B_*NH_);
    attn_fp16<<<g2, 256, ATTN_SMEM>>>(qkvh_p, vth_p, att_p);

    // 3) Output projection (fp16) -> natural fp32 out
    dim3 g3(C_/128, M_/128);
    gemm_fp16<false><<<g3, 128, GEMM_SMEM>>>(att_p, wp_p, bproj, out, nullptr,
                                             M_, C_, C_);
}

// round 16
// speedup vs baseline: 1.8657x; 1.0875x over previous
#include <cuda_runtime.h>
#include <cuda_fp16.h>
#include <cstdint>

// Problem constants
#define B_    2
#define T_    2048
#define C_    1024
#define NH_   16
#define HD_   64
#define M_    (B_ * T_)     // 4096
#define NQKV_ (3 * C_)      // 3072

// Scratch (device globals: allocation-free)
__device__ __half g_qkvh[(size_t)M_ * NQKV_];    // qkv (half, pair-perm8 along d)
__device__ __half g_vth[(size_t)B_ * C_ * T_];   // V^T [b][c'][t] (half, pair-perm8 t)
__device__ __half g_att[(size_t)M_ * C_];        // attention out (half, pair-perm8)
__device__ __half g_xh [(size_t)M_ * C_];        // x -> half, pair-perm8
__device__ __half g_wqkvh[(size_t)C_ * NQKV_];   // Wqkv^T -> half [N][K], pair-perm8
__device__ __half g_wprojh[(size_t)C_ * C_];     // Wproj^T -> half [N][K], pair-perm8

// ---------------------------------------------------------------------------
// helpers
// ---------------------------------------------------------------------------
__device__ __forceinline__ float ex2f(float x) {
    float y;
    asm volatile("ex2.approx.ftz.f32 %0, %1;" : "=f"(y) : "f"(x));
    return y;
}
__device__ __forceinline__ void cp16(uint32_t dsm, const void* src) {
    asm volatile("cp.async.ca.shared.global [%0], [%1], 16;" :: "r"(dsm), "l"(src));
}
#define CP_COMMIT() asm volatile("cp.async.commit_group;")
#define CP_WAIT0()  asm volatile("cp.async.wait_group 0;")

// within-8 permutation (forward map): true unit k -> storage position.
__device__ __host__ __forceinline__ int perm8(int k) { return ((k & 3) << 1) | (k >> 2); }

// fp16 warp mma: K=16 per instruction, fp32 accumulate
#define MMA_F16(d, a0,a1,a2,a3, b0,b1)                                    \
    asm volatile("mma.sync.aligned.m16n8k16.row.col.f32.f16.f16.f32 "     \
        "{%0,%1,%2,%3}, {%4,%5,%6,%7}, {%8,%9}, {%0,%1,%2,%3};"           \
        : "+f"((d)[0]), "+f"((d)[1]), "+f"((d)[2]), "+f"((d)[3])          \
        : "r"(a0), "r"(a1), "r"(a2), "r"(a3), "r"(b0), "r"(b1))

// ---------------------------------------------------------------------------
// cvt kernels: fp32 -> half with pair-perm8 within 16-half groups.
// ---------------------------------------------------------------------------
__global__ void cvt_x_h(const float4* __restrict__ in,
                        __half2* __restrict__ out, int n16) {
    int i = blockIdx.x * blockDim.x + threadIdx.x;
    if (i < n16) {
        float4 v0 = in[4*i], v1 = in[4*i+1], v2 = in[4*i+2], v3 = in[4*i+3];
        __half2* o = out + 8*i;
        o[0] = __floats2half2_rn(v0.x, v0.y);   // pair 0
        o[1] = __floats2half2_rn(v2.x, v2.y);   // pair 4
        o[2] = __floats2half2_rn(v0.z, v0.w);   // pair 1
        o[3] = __floats2half2_rn(v2.z, v2.w);   // pair 5
        o[4] = __floats2half2_rn(v1.x, v1.y);   // pair 2
        o[5] = __floats2half2_rn(v3.x, v3.y);   // pair 6
        o[6] = __floats2half2_rn(v1.z, v1.w);   // pair 3
        o[7] = __floats2half2_rn(v3.z, v3.w);   // pair 7
    }
}

// W [K][N] fp32 -> W' [N][K] half (pair-perm8 within 16-k groups)
__global__ void cvt_transpose_h(const float* __restrict__ in,
                                __half* __restrict__ out, int K, int N) {
    __shared__ float t[32][33];
    const int k0 = blockIdx.y * 32, n0 = blockIdx.x * 32;
    const int tx = threadIdx.x, ty = threadIdx.y;
#pragma unroll
    for (int i = 0; i < 4; i++)
        t[ty + 8*i][tx] = in[(size_t)(k0 + ty + 8*i) * N + n0 + tx];
    __syncthreads();
    const int kpos = (tx & ~15) | (perm8((tx >> 1) & 7) << 1) | (tx & 1);
#pragma unroll
    for (int i = 0; i < 4; i++) {
        int n = ty + 8*i;
        out[(size_t)(n0 + n) * K + k0 + kpos] = __float2half_rn(t[tx][n]);
    }
}

// V section of qkvh [r][c'] -> vt[b][c'][tpos] (half), pair-perm8 along t.
__global__ void vt_transpose(const __half* __restrict__ qkvh,
                             __half* __restrict__ vt) {
    __shared__ __half t[32][33];
    const int c0 = blockIdx.x * 32, r0 = blockIdx.y * 32;
    const int tx = threadIdx.x, ty = threadIdx.y;
#pragma unroll
    for (int i = 0; i < 4; i++)
        t[ty + 8*i][tx] = qkvh[(size_t)(r0 + ty + 8*i) * NQKV_ + 2*C_ + c0 + tx];
    __syncthreads();
    const int b = r0 >> 11;            // T_ = 2048
    const int tbase = r0 & (T_ - 1);
    const int v = tx & 15;
    const int tpos = (tx & ~15) | (perm8((v >> 1) & 7) << 1) | (v & 1);
#pragma unroll
    for (int i = 0; i < 4; i++) {
        int c = c0 + ty + 8*i;
        vt[((size_t)b * C_ + c) * T_ + tbase + tpos] = t[tx][ty + 8*i];
    }
}

// ---------------------------------------------------------------------------
// FP16 GEMM + bias.  C[M,N] = A[M,K] @ B'[N,K]^T + bias.
// 128 threads / 4 warps, warp tile 64x64, block 128x128x64(k halves),
// m16n8k16, 2-stage cp.async, single barrier per k-tile.
// PERM_OUT: HALF output, pair-perm8 positions (qkv/att format).
// ---------------------------------------------------------------------------
#define ST_H 80
#define STG_H (128 * ST_H)                  // halves per operand per stage
#define GEMM_SMEM (2 * 2 * STG_H * 2)       // 81920 B

template<bool PERM_OUT>
__global__ __launch_bounds__(128, 2)
void gemm_fp16(const __half* __restrict__ A, const __half* __restrict__ Bm,
               const float* __restrict__ bias, float* __restrict__ Cm,
               __half* __restrict__ Ch, int M, int N, int K) {
    extern __shared__ __half smh[];

    const int tid  = threadIdx.x;
    const int lane = tid & 31, warp = tid >> 5;
    const int wm = warp >> 1, wn = warp & 1;     // 2x2 warp grid, 64x64 tiles
    const int g  = lane >> 2, t4 = lane & 3;
    const int row0 = blockIdx.y * 128, col0 = blockIdx.x * 128;

    const uint32_t sbase = (uint32_t)__cvta_generic_to_shared(smh);

    auto issue = [&](int kt) {
        const int buf = kt & 1;
        const uint32_t sA = sbase + (uint32_t)(buf * 2 * STG_H) * 2;
        const uint32_t sB = sA + (uint32_t)STG_H * 2;
#pragma unroll
        for (int i = 0; i < 8; i++) {
            int idx = tid + 128 * i;
            int r = idx >> 3, s8 = idx & 7;
            cp16(sA + (uint32_t)(r * ST_H * 2 + s8 * 16),
                 &A[(size_t)(row0 + r) * K + kt * 64 + s8 * 8]);
        }
#pragma unroll
        for (int i = 0; i < 8; i++) {
            int idx = tid + 128 * i;
            int r = idx >> 3, s8 = idx & 7;
            cp16(sB + (uint32_t)(r * ST_H * 2 + s8 * 16),
                 &Bm[(size_t)(col0 + r) * K + kt * 64 + s8 * 8]);
        }
    };

    float acc[4][8][4];
#pragma unroll
    for (int mt = 0; mt < 4; mt++)
#pragma unroll
        for (int nt = 0; nt < 8; nt++)
#pragma unroll
            for (int c = 0; c < 4; c++) acc[mt][nt][c] = 0.f;

    const int KT = K >> 6;
    issue(0); CP_COMMIT();

    for (int kt = 0; kt < KT; kt++) {
        CP_WAIT0();
        __syncthreads();
        if (kt + 1 < KT) { issue(kt + 1); CP_COMMIT(); }

        const __half* Ab = smh + (kt & 1) * 2 * STG_H;
        const __half* Bb = Ab + STG_H;

#pragma unroll
        for (int kki = 0; kki < 4; kki++) {
            const int kk = kki * 16;
            uint2 ral[4], rah[4];
#pragma unroll
            for (int mt = 0; mt < 4; mt++) {
                const __half* ap = Ab + (wm*64 + mt*16 + g) * ST_H + kk + 4*t4;
                ral[mt] = *reinterpret_cast<const uint2*>(ap);
                rah[mt] = *reinterpret_cast<const uint2*>(ap + 8*ST_H);
            }
#pragma unroll
            for (int nt = 0; nt < 8; nt++) {
                uint2 rb = *reinterpret_cast<const uint2*>(
                    Bb + (wn*64 + nt*8 + g) * ST_H + kk + 4*t4);
#pragma unroll
                for (int mt = 0; mt < 4; mt++)
                    MMA_F16(acc[mt][nt], ral[mt].x, rah[mt].x,
                            ral[mt].y, rah[mt].y, rb.x, rb.y);
            }
        }
    }

    // epilogue: + bias (true columns)
#pragma unroll
    for (int mt = 0; mt < 4; mt++) {
        const int rA = row0 + wm*64 + mt*16 + g;
        const int rB = rA + 8;
#pragma unroll
        for (int nt = 0; nt < 8; nt++) {
            const int c = col0 + wn*64 + nt*8 + 2*t4;
            const float b0 = bias[c], b1 = bias[c + 1];
            float v0 = acc[mt][nt][0] + b0, v1 = acc[mt][nt][1] + b1;
            float v2 = acc[mt][nt][2] + b0, v3 = acc[mt][nt][3] + b1;
            if (PERM_OUT) {
                // true pair p=(nt&1)*4+t4 of 16-group -> unit (t4<<1)|(nt&1)
                const int hc = col0 + wn*64 + ((nt >> 1) << 4)
                             + ((((t4 << 1) | (nt & 1))) << 1);
                *reinterpret_cast<__half2*>(&Ch[(size_t)rA * N + hc]) =
                    __floats2half2_rn(v0, v1);
                *reinterpret_cast<__half2*>(&Ch[(size_t)rB * N + hc]) =
                    __floats2half2_rn(v2, v3);
            } else {
                *reinterpret_cast<float2*>(&Cm[(size_t)rA * N + c]) = make_float2(v0, v1);
                *reinterpret_cast<float2*>(&Cm[(size_t)rB * N + c]) = make_float2(v2, v3);
            }
        }
    }
}

// ---------------------------------------------------------------------------
// FP16 tensor-core flash attention, PAIR-BALANCED grid.
// grid.x = 8: CTA i processes q-tiles {15-i, i} sequentially -> every CTA
// does exactly 34 kv-tiles; 256 CTAs = ONE balanced wave at 2 CTA/SM.
// Q/K half pair-perm8 along d; V^T half pair-perm8 along t; m16n8k16;
// softmax fp32 exp2-domain; O in V-position space -> direct half2 write.
// ---------------------------------------------------------------------------
#define AH 80
#define AKV_TILE (64 * AH + 64 * AH)          // halves: K + Vt per stage
#define ATTN_SMEM ((128*AH + 2*AKV_TILE + 128*AH) * 2)   // 81920 B

#define MASKVAL (-6e30f)
#define MINIT   (-1e30f)

__global__ __launch_bounds__(256, 2)
void attn_fp16(const __half* __restrict__ qkvh, const __half* __restrict__ vth,
               __half* __restrict__ att) {
    extern __shared__ __half smh[];
    __half* Qs  = smh;                       // [128][AH]
    __half* KV0 = Qs + 128*AH;               // 2 stages: K[64][AH] + Vt[64][AH]
    __half* Ps  = KV0 + 2*AKV_TILE;          // [128][AH]

    const int tid  = threadIdx.x;
    const int lane = tid & 31, warp = tid >> 5;
    const int g = lane >> 2, t4 = lane & 3;
    const int bh = blockIdx.y;
    const int b = bh >> 4, h = bh & 15;
    const int rb = warp * 16;
    const int NQT = T_ / 128;                // 16 q-tiles

    const __half* kbase = qkvh + (size_t)b*T_*NQKV_ + h*HD_ + C_;
    const __half* vtb   = vth + ((size_t)b*C_ + h*HD_) * T_;

    const uint32_t sq  = (uint32_t)__cvta_generic_to_shared(Qs);
    const uint32_t skv = (uint32_t)__cvta_generic_to_shared(KV0);

    auto issue = [&](int kvb) {
        const uint32_t sK = skv + (uint32_t)((kvb & 1) * AKV_TILE) * 2;
        const uint32_t sV = sK + (uint32_t)(64 * AH) * 2;
        const int jb = kvb * 64;
#pragma unroll
        for (int i = 0; i < 2; i++) {
            int idx = tid + 256 * i;
            int j = idx >> 3, s8 = idx & 7;
            cp16(sK + (uint32_t)(j*AH + s8*8) * 2,
                 &kbase[(size_t)(jb + j)*NQKV_ + s8*8]);
        }
#pragma unroll
        for (int i = 0; i < 2; i++) {
            int idx = tid + 256 * i;
            int d = idx >> 3, s8 = idx & 7;
            cp16(sV + (uint32_t)(d*AH + s8*8) * 2,
                 &vtb[(size_t)d * T_ + jb + s8*8]);
        }
    };

    const float SC = 0.125f * 1.44269504088896340736f;   // 1/sqrt(64)*log2(e)

    // Pair-balanced q-tile loop: heavy tile (NQT-1-bx) then light tile (bx).
#pragma unroll 1
    for (int sub = 0; sub < 2; sub++) {
        const int qb = sub ? (int)blockIdx.x : (NQT - 1 - (int)blockIdx.x);
        const int m0 = qb * 128;
        const __half* qbase = qkvh + ((size_t)b*T_ + m0)*NQKV_ + h*HD_;

        // Q tile (raw; softmax scale folded post-mma)
#pragma unroll
        for (int i = 0; i < 4; i++) {
            int idx = tid + 256 * i;
            int r = idx >> 3, s8 = idx & 7;
            cp16(sq + (uint32_t)(r*AH + s8*8) * 2, &qbase[(size_t)r*NQKV_ + s8*8]);
        }
        issue(0); CP_COMMIT();

        float o[8][4];
        float mrow[2] = {MINIT, MINIT}, lrow[2] = {0.f, 0.f};
#pragma unroll
        for (int nt = 0; nt < 8; nt++)
#pragma unroll
            for (int c = 0; c < 4; c++) o[nt][c] = 0.f;

        const int nkv = 2*qb + 2;
        for (int kvb = 0; kvb < nkv; kvb++) {
            const int jb = kvb * 64;
            CP_WAIT0();
            __syncthreads();
            if (kvb + 1 < nkv) { issue(kvb + 1); CP_COMMIT(); }

            const __half* Ks = KV0 + (kvb & 1) * AKV_TILE;
            const __half* Vs = Ks + 64 * AH;

            if (jb > m0 + rb + 15) continue;

            // ---- S = Q @ K^T (both pair-perm8 along d: invariant) ----
            float s[8][4];
#pragma unroll
            for (int nt = 0; nt < 8; nt++)
#pragma unroll
                for (int c = 0; c < 4; c++) s[nt][c] = 0.f;

#pragma unroll
            for (int kk = 0; kk < 64; kk += 16) {
                const __half* ap = Qs + (rb + g)*AH + kk + 4*t4;
                uint2 qa0 = *reinterpret_cast<const uint2*>(ap);
                uint2 qa1 = *reinterpret_cast<const uint2*>(ap + 8*AH);
#pragma unroll
                for (int nt = 0; nt < 8; nt++) {
                    uint2 kf = *reinterpret_cast<const uint2*>(
                        Ks + (nt*8 + g)*AH + kk + 4*t4);
                    MMA_F16(s[nt], qa0.x, qa1.x, qa0.y, qa1.y, kf.x, kf.y);
                }
            }

            // ---- scale, causal mask (true j coords; K rows natural) ----
#pragma unroll
            for (int nt = 0; nt < 8; nt++)
#pragma unroll
                for (int c = 0; c < 4; c++) s[nt][c] *= SC;
            if (jb + 63 > m0 + rb) {
                const int r0 = m0 + rb + g, r1 = r0 + 8;
#pragma unroll
                for (int nt = 0; nt < 8; nt++) {
                    int cb = jb + nt*8 + 2*t4;
                    if (cb     > r0) s[nt][0] = MASKVAL;
                    if (cb + 1 > r0) s[nt][1] = MASKVAL;
                    if (cb     > r1) s[nt][2] = MASKVAL;
                    if (cb + 1 > r1) s[nt][3] = MASKVAL;
                }
            }

            // ---- online softmax (exp2 domain) ----
            float mx0 = MINIT, mx1 = MINIT;
#pragma unroll
            for (int nt = 0; nt < 8; nt++) {
                mx0 = fmaxf(mx0, fmaxf(s[nt][0], s[nt][1]));
                mx1 = fmaxf(mx1, fmaxf(s[nt][2], s[nt][3]));
            }
            mx0 = fmaxf(mx0, __shfl_xor_sync(0xffffffffu, mx0, 1));
            mx0 = fmaxf(mx0, __shfl_xor_sync(0xffffffffu, mx0, 2));
            mx1 = fmaxf(mx1, __shfl_xor_sync(0xffffffffu, mx1, 1));
            mx1 = fmaxf(mx1, __shfl_xor_sync(0xffffffffu, mx1, 2));
            const float mn0 = fmaxf(mrow[0], mx0), mn1 = fmaxf(mrow[1], mx1);
            const float al0 = ex2f(mrow[0] - mn0), al1 = ex2f(mrow[1] - mn1);
            mrow[0] = mn0; mrow[1] = mn1;

            float ls0 = 0.f, ls1 = 0.f;
            __half* p0 = Ps + (rb + g)*AH;
            __half* p1 = Ps + (rb + g + 8)*AH;
#pragma unroll
            for (int nt = 0; nt < 8; nt++) {
                s[nt][0] = ex2f(s[nt][0] - mn0);
                s[nt][1] = ex2f(s[nt][1] - mn0);
                s[nt][2] = ex2f(s[nt][2] - mn1);
                s[nt][3] = ex2f(s[nt][3] - mn1);
                ls0 += s[nt][0] + s[nt][1];
                ls1 += s[nt][2] + s[nt][3];
                o[nt][0] *= al0; o[nt][1] *= al0;
                o[nt][2] *= al1; o[nt][3] *= al1;
                // stage P half, pair-perm8 along j
                const int hoff = ((nt >> 1) << 4) + ((((t4 << 1) | (nt & 1))) << 1);
                *reinterpret_cast<__half2*>(p0 + hoff) =
                    __floats2half2_rn(s[nt][0], s[nt][1]);
                *reinterpret_cast<__half2*>(p1 + hoff) =
                    __floats2half2_rn(s[nt][2], s[nt][3]);
            }
            ls0 += __shfl_xor_sync(0xffffffffu, ls0, 1);
            ls0 += __shfl_xor_sync(0xffffffffu, ls0, 2);
            ls1 += __shfl_xor_sync(0xffffffffu, ls1, 1);
            ls1 += __shfl_xor_sync(0xffffffffu, ls1, 2);
            lrow[0] = lrow[0]*al0 + ls0;
            lrow[1] = lrow[1]*al1 + ls1;

            __syncwarp();

            // ---- O += P @ V^T (both pair-perm8 along j: invariant) ----
#pragma unroll
            for (int kk = 0; kk < 64; kk += 16) {
                const __half* ap = Ps + (rb + g)*AH + kk + 4*t4;
                uint2 pa0 = *reinterpret_cast<const uint2*>(ap);
                uint2 pa1 = *reinterpret_cast<const uint2*>(ap + 8*AH);
#pragma unroll
                for (int nt = 0; nt < 8; nt++) {
                    uint2 vf = *reinterpret_cast<const uint2*>(
                        Vs + (nt*8 + g)*AH + kk + 4*t4);
                    MMA_F16(o[nt], pa0.x, pa1.x, pa0.y, pa1.y, vf.x, vf.y);
                }
            }
        }

        // ---- epilogue: O columns are V^T-row positions == att layout ----
        const float inv0 = 1.0f / lrow[0], inv1 = 1.0f / lrow[1];
        const size_t r0 = (size_t)b*T_ + m0 + rb + g;
        const size_t r1 = r0 + 8;
#pragma unroll
        for (int nt = 0; nt < 8; nt++) {
            const int hc = h*HD_ + nt*8 + 2*t4;
            *reinterpret_cast<__half2*>(&att[r0*C_ + hc]) =
                __floats2half2_rn(o[nt][0] * inv0, o[nt][1] * inv0);
            *reinterpret_cast<__half2*>(&att[r1*C_ + hc]) =
                __floats2half2_rn(o[nt][2] * inv1, o[nt][3] * inv1);
        }

        __syncthreads();   // all warps done with Qs/KV0/Ps before next q-tile
    }
}

// ---------------------------------------------------------------------------
// Launch
// ---------------------------------------------------------------------------
extern "C" void kernel_launch(void* const* d_in, const int* in_sizes, int n_in,
                              void* d_out, int out_size) {
    const float* x     = (const float*)d_in[0];
    const float* Wqkv  = (const float*)d_in[1];
    const float* bqkv  = (const float*)d_in[2];
    const float* Wproj = (const float*)d_in[3];
    const float* bproj = (const float*)d_in[4];
    float* out = (float*)d_out;

    __half *qkvh_p, *vth_p, *att_p, *xh_p, *wq_p, *wp_p;
    cudaGetSymbolAddress((void**)&qkvh_p, g_qkvh);
    cudaGetSymbolAddress((void**)&vth_p,  g_vth);
    cudaGetSymbolAddress((void**)&att_p,  g_att);
    cudaGetSymbolAddress((void**)&xh_p,   g_xh);
    cudaGetSymbolAddress((void**)&wq_p,   g_wqkvh);
    cudaGetSymbolAddress((void**)&wp_p,   g_wprojh);

    cudaFuncSetAttribute(gemm_fp16<true>,
                         cudaFuncAttributeMaxDynamicSharedMemorySize, GEMM_SMEM);
    cudaFuncSetAttribute(gemm_fp16<false>,
                         cudaFuncAttributeMaxDynamicSharedMemorySize, GEMM_SMEM);
    cudaFuncSetAttribute(attn_fp16,
                         cudaFuncAttributeMaxDynamicSharedMemorySize, ATTN_SMEM);

    // 0) operand prep
    cvt_x_h<<<(M_*C_/16)/256, 256>>>((const float4*)x, (__half2*)xh_p, M_*C_/16);
    {
        dim3 blk(32, 8);
        dim3 gq(NQKV_/32, C_/32);
        cvt_transpose_h<<<gq, blk>>>(Wqkv, wq_p, C_, NQKV_);
        dim3 gp(C_/32, C_/32);
        cvt_transpose_h<<<gp, blk>>>(Wproj, wp_p, C_, C_);
    }

    // 1) QKV GEMM (fp16) -> half pair-perm8 qkv
    dim3 g1(NQKV_/128, M_/128);
    gemm_fp16<true><<<g1, 128, GEMM_SMEM>>>(xh_p, wq_p, bqkv, nullptr, qkvh_p,
                                            M_, NQKV_, C_);

    // 1b) V^T (pair-perm8 along t)
    {
        dim3 blk(32, 8);
        dim3 gv(C_/32, M_/32);
        vt_transpose<<<gv, blk>>>(qkvh_p, vth_p);
    }

    // 2) FP16 flash attention, pair-balanced single wave -> half att
    dim3 g2(T_/256, B_*NH_);    // 8 x 32 = 256 CTAs
    attn_fp16<<<g2, 256, ATTN_SMEM>>>(qkvh_p, vth_p, att_p);

    // 3) Output projection (fp16) -> natural fp32 out
    dim3 g3(C_/128, M_/128);
    gemm_fp16<false><<<g3, 128, GEMM_SMEM>>>(att_p, wp_p, bproj, out, nullptr,
                                             M_, C_, C_);
}

// round 17
// speedup vs baseline: 2.0163x; 1.0807x over previous
#include <cuda_runtime.h>
#include <cuda_fp16.h>
#include <cstdint>

// Problem constants
#define B_    2
#define T_    2048
#define C_    1024
#define NH_   16
#define HD_   64
#define M_    (B_ * T_)     // 4096
#define NQKV_ (3 * C_)      // 3072

// Scratch (device globals: allocation-free)
__device__ __half g_qkvh[(size_t)M_ * NQKV_];    // qkv (half, pair-perm8 along d)
__device__ __half g_vth[(size_t)B_ * C_ * T_];   // V^T [b][c'][t] (half, pair-perm8 t)
__device__ __half g_att[(size_t)M_ * C_];        // attention out (half, pair-perm8)
__device__ __half g_xh [(size_t)M_ * C_];        // x -> half, pair-perm8
__device__ __half g_wqkvh[(size_t)C_ * NQKV_];   // Wqkv^T -> half [N][K], pair-perm8
__device__ __half g_wprojh[(size_t)C_ * C_];     // Wproj^T -> half [N][K], pair-perm8

// ---------------------------------------------------------------------------
// helpers
// ---------------------------------------------------------------------------
__device__ __forceinline__ float ex2f(float x) {
    float y;
    asm volatile("ex2.approx.ftz.f32 %0, %1;" : "=f"(y) : "f"(x));
    return y;
}
__device__ __forceinline__ void cp16(uint32_t dsm, const void* src) {
    asm volatile("cp.async.ca.shared.global [%0], [%1], 16;" :: "r"(dsm), "l"(src));
}
#define CP_COMMIT() asm volatile("cp.async.commit_group;")
#define CP_WAIT0()  asm volatile("cp.async.wait_group 0;")

// within-8 permutation (forward map): true unit k -> storage position.
__device__ __host__ __forceinline__ int perm8(int k) { return ((k & 3) << 1) | (k >> 2); }

// fp16 warp mma: K=16 per instruction, fp32 accumulate
#define MMA_F16(d, a0,a1,a2,a3, b0,b1)                                    \
    asm volatile("mma.sync.aligned.m16n8k16.row.col.f32.f16.f16.f32 "     \
        "{%0,%1,%2,%3}, {%4,%5,%6,%7}, {%8,%9}, {%0,%1,%2,%3};"           \
        : "+f"((d)[0]), "+f"((d)[1]), "+f"((d)[2]), "+f"((d)[3])          \
        : "r"(a0), "r"(a1), "r"(a2), "r"(a3), "r"(b0), "r"(b1))

// ldmatrix x4: four 8x8 b16 matrices; addr = per-lane shared u32
#define LDSM_X4(r0,r1,r2,r3, addr)                                         \
    asm volatile("ldmatrix.sync.aligned.m8n8.x4.shared.b16 {%0,%1,%2,%3}, [%4];" \
        : "=r"(r0), "=r"(r1), "=r"(r2), "=r"(r3) : "r"(addr))

// ---------------------------------------------------------------------------
// cvt kernels: fp32 -> half with pair-perm8 within 16-half groups.
// ---------------------------------------------------------------------------
__global__ void cvt_x_h(const float4* __restrict__ in,
                        __half2* __restrict__ out, int n16) {
    int i = blockIdx.x * blockDim.x + threadIdx.x;
    if (i < n16) {
        float4 v0 = in[4*i], v1 = in[4*i+1], v2 = in[4*i+2], v3 = in[4*i+3];
        __half2* o = out + 8*i;
        o[0] = __floats2half2_rn(v0.x, v0.y);   // pair 0
        o[1] = __floats2half2_rn(v2.x, v2.y);   // pair 4
        o[2] = __floats2half2_rn(v0.z, v0.w);   // pair 1
        o[3] = __floats2half2_rn(v2.z, v2.w);   // pair 5
        o[4] = __floats2half2_rn(v1.x, v1.y);   // pair 2
        o[5] = __floats2half2_rn(v3.x, v3.y);   // pair 6
        o[6] = __floats2half2_rn(v1.z, v1.w);   // pair 3
        o[7] = __floats2half2_rn(v3.z, v3.w);   // pair 7
    }
}

// W [K][N] fp32 -> W' [N][K] half (pair-perm8 within 16-k groups)
__global__ void cvt_transpose_h(const float* __restrict__ in,
                                __half* __restrict__ out, int K, int N) {
    __shared__ float t[32][33];
    const int k0 = blockIdx.y * 32, n0 = blockIdx.x * 32;
    const int tx = threadIdx.x, ty = threadIdx.y;
#pragma unroll
    for (int i = 0; i < 4; i++)
        t[ty + 8*i][tx] = in[(size_t)(k0 + ty + 8*i) * N + n0 + tx];
    __syncthreads();
    const int kpos = (tx & ~15) | (perm8((tx >> 1) & 7) << 1) | (tx & 1);
#pragma unroll
    for (int i = 0; i < 4; i++) {
        int n = ty + 8*i;
        out[(size_t)(n0 + n) * K + k0 + kpos] = __float2half_rn(t[tx][n]);
    }
}

// V section of qkvh [r][c'] -> vt[b][c'][tpos] (half), pair-perm8 along t.
__global__ void vt_transpose(const __half* __restrict__ qkvh,
                             __half* __restrict__ vt) {
    __shared__ __half t[32][33];
    const int c0 = blockIdx.x * 32, r0 = blockIdx.y * 32;
    const int tx = threadIdx.x, ty = threadIdx.y;
#pragma unroll
    for (int i = 0; i < 4; i++)
        t[ty + 8*i][tx] = qkvh[(size_t)(r0 + ty + 8*i) * NQKV_ + 2*C_ + c0 + tx];
    __syncthreads();
    const int b = r0 >> 11;            // T_ = 2048
    const int tbase = r0 & (T_ - 1);
    const int v = tx & 15;
    const int tpos = (tx & ~15) | (perm8((v >> 1) & 7) << 1) | (v & 1);
#pragma unroll
    for (int i = 0; i < 4; i++) {
        int c = c0 + ty + 8*i;
        vt[((size_t)b * C_ + c) * T_ + tbase + tpos] = t[tx][ty + 8*i];
    }
}

// ---------------------------------------------------------------------------
// FP16 GEMM + bias.  C[M,N] = A[M,K] @ B'[N,K]^T + bias.
// 128 threads / 4 warps, warp tile 64x64, block 128x128x64(k halves),
// m16n8k16, 2-stage cp.async, single barrier per k-tile.
// Fragments via ldmatrix.x4 (stride 72 halves = 144B: LDSM phases cover all
// 32 banks exactly -> conflict-free).
// PERM_OUT: HALF output, pair-perm8 positions (qkv/att format).
// ---------------------------------------------------------------------------
#define ST_H 72
#define STG_B (128 * ST_H * 2)              // bytes per operand per stage (18432)
#define GEMM_SMEM (4 * STG_B)               // 73728 B

template<bool PERM_OUT>
__global__ __launch_bounds__(128, 2)
void gemm_fp16(const __half* __restrict__ A, const __half* __restrict__ Bm,
               const float* __restrict__ bias, float* __restrict__ Cm,
               __half* __restrict__ Ch, int M, int N, int K) {
    extern __shared__ __half smh[];

    const int tid  = threadIdx.x;
    const int lane = tid & 31, warp = tid >> 5;
    const int wm = warp >> 1, wn = warp & 1;     // 2x2 warp grid, 64x64 tiles
    const int g  = lane >> 2, t4 = lane & 3;
    const int row0 = blockIdx.y * 128, col0 = blockIdx.x * 128;

    const uint32_t sbase = (uint32_t)__cvta_generic_to_shared(smh);

    // ldmatrix per-lane offsets (bytes)
    const uint32_t aOff = (uint32_t)((wm*64 + (lane & 15)) * 144 + (lane >> 4) * 16);
    const uint32_t bOff = (uint32_t)((wn*64 + ((lane >> 4) & 1) * 8 + (lane & 7)) * 144
                                     + ((lane >> 3) & 1) * 16);

    auto issue = [&](int kt) {
        const uint32_t sA = sbase + (uint32_t)((kt & 1) * 2 * STG_B);
        const uint32_t sB = sA + STG_B;
#pragma unroll
        for (int i = 0; i < 8; i++) {
            int idx = tid + 128 * i;
            int r = idx >> 3, s8 = idx & 7;
            cp16(sA + (uint32_t)(r * 144 + s8 * 16),
                 &A[(size_t)(row0 + r) * K + kt * 64 + s8 * 8]);
        }
#pragma unroll
        for (int i = 0; i < 8; i++) {
            int idx = tid + 128 * i;
            int r = idx >> 3, s8 = idx & 7;
            cp16(sB + (uint32_t)(r * 144 + s8 * 16),
                 &Bm[(size_t)(col0 + r) * K + kt * 64 + s8 * 8]);
        }
    };

    float acc[4][8][4];
#pragma unroll
    for (int mt = 0; mt < 4; mt++)
#pragma unroll
        for (int nt = 0; nt < 8; nt++)
#pragma unroll
            for (int c = 0; c < 4; c++) acc[mt][nt][c] = 0.f;

    const int KT = K >> 6;
    issue(0); CP_COMMIT();

    for (int kt = 0; kt < KT; kt++) {
        CP_WAIT0();
        __syncthreads();
        if (kt + 1 < KT) { issue(kt + 1); CP_COMMIT(); }

        const uint32_t aBase = sbase + (uint32_t)((kt & 1) * 2 * STG_B) + aOff;
        const uint32_t bBase = aBase - aOff + STG_B + bOff;

#pragma unroll
        for (int kki = 0; kki < 4; kki++) {
            const uint32_t ka = aBase + kki * 32;
            const uint32_t kb = bBase + kki * 32;
            uint32_t ra[4][4];
#pragma unroll
            for (int mt = 0; mt < 4; mt++)
                LDSM_X4(ra[mt][0], ra[mt][1], ra[mt][2], ra[mt][3],
                        ka + (uint32_t)(mt * 16 * 144));
#pragma unroll
            for (int ntp = 0; ntp < 4; ntp++) {
                uint32_t rb0, rb1, rb2, rb3;
                LDSM_X4(rb0, rb1, rb2, rb3, kb + (uint32_t)(ntp * 16 * 144));
#pragma unroll
                for (int mt = 0; mt < 4; mt++)
                    MMA_F16(acc[mt][2*ntp], ra[mt][0], ra[mt][1],
                            ra[mt][2], ra[mt][3], rb0, rb1);
#pragma unroll
                for (int mt = 0; mt < 4; mt++)
                    MMA_F16(acc[mt][2*ntp+1], ra[mt][0], ra[mt][1],
                            ra[mt][2], ra[mt][3], rb2, rb3);
            }
        }
    }

    // epilogue: + bias (true columns)
#pragma unroll
    for (int mt = 0; mt < 4; mt++) {
        const int rA = row0 + wm*64 + mt*16 + g;
        const int rB = rA + 8;
#pragma unroll
        for (int nt = 0; nt < 8; nt++) {
            const int c = col0 + wn*64 + nt*8 + 2*t4;
            const float b0 = bias[c], b1 = bias[c + 1];
            float v0 = acc[mt][nt][0] + b0, v1 = acc[mt][nt][1] + b1;
            float v2 = acc[mt][nt][2] + b0, v3 = acc[mt][nt][3] + b1;
            if (PERM_OUT) {
                // true pair p=(nt&1)*4+t4 of 16-group -> unit (t4<<1)|(nt&1)
                const int hc = col0 + wn*64 + ((nt >> 1) << 4)
                             + ((((t4 << 1) | (nt & 1))) << 1);
                *reinterpret_cast<__half2*>(&Ch[(size_t)rA * N + hc]) =
                    __floats2half2_rn(v0, v1);
                *reinterpret_cast<__half2*>(&Ch[(size_t)rB * N + hc]) =
                    __floats2half2_rn(v2, v3);
            } else {
                *reinterpret_cast<float2*>(&Cm[(size_t)rA * N + c]) = make_float2(v0, v1);
                *reinterpret_cast<float2*>(&Cm[(size_t)rB * N + c]) = make_float2(v2, v3);
            }
        }
    }
}

// ---------------------------------------------------------------------------
// FP16 tensor-core flash attention, PAIR-BALANCED grid, ldmatrix fragments.
// grid.x = 8: CTA i processes q-tiles {15-i, i} -> every CTA does exactly
// 34 kv-tiles; 256 CTAs = ONE balanced wave at 2 CTA/SM.
// ---------------------------------------------------------------------------
#define AH 72
#define AROW 144                                    // bytes per smem row
#define AT_TILE (64 * AH)                           // halves per 64-row tile
#define AKV_TILE (2 * AT_TILE)                      // K + Vt per stage
#define ATTN_SMEM ((128*AH + 2*AKV_TILE + 128*AH) * 2)   // 73728 B

#define MASKVAL (-6e30f)
#define MINIT   (-1e30f)

__global__ __launch_bounds__(256, 2)
void attn_fp16(const __half* __restrict__ qkvh, const __half* __restrict__ vth,
               __half* __restrict__ att) {
    extern __shared__ __half smh[];
    __half* Qs  = smh;                       // [128][AH]
    __half* KV0 = Qs + 128*AH;               // 2 stages: K[64][AH] + Vt[64][AH]
    __half* Ps  = KV0 + 2*AKV_TILE;          // [128][AH]

    const int tid  = threadIdx.x;
    const int lane = tid & 31, warp = tid >> 5;
    const int g = lane >> 2, t4 = lane & 3;
    const int bh = blockIdx.y;
    const int b = bh >> 4, h = bh & 15;
    const int rb = warp * 16;
    const int NQT = T_ / 128;                // 16 q-tiles

    const __half* kbase = qkvh + (size_t)b*T_*NQKV_ + h*HD_ + C_;
    const __half* vtb   = vth + ((size_t)b*C_ + h*HD_) * T_;

    const uint32_t sq  = (uint32_t)__cvta_generic_to_shared(Qs);
    const uint32_t skv = (uint32_t)__cvta_generic_to_shared(KV0);
    const uint32_t sp  = (uint32_t)__cvta_generic_to_shared(Ps);

    // ldmatrix per-lane offsets (bytes)
    const uint32_t aLOff = (uint32_t)((lane & 15) * AROW + (lane >> 4) * 16);
    const uint32_t bLOff = (uint32_t)((((lane >> 4) & 1) * 8 + (lane & 7)) * AROW
                                      + ((lane >> 3) & 1) * 16);

    auto issue = [&](int kvb) {
        const uint32_t sK = skv + (uint32_t)((kvb & 1) * AKV_TILE) * 2;
        const uint32_t sV = sK + (uint32_t)AT_TILE * 2;
        const int jb = kvb * 64;
#pragma unroll
        for (int i = 0; i < 2; i++) {
            int idx = tid + 256 * i;
            int j = idx >> 3, s8 = idx & 7;
            cp16(sK + (uint32_t)(j*AROW + s8*16),
                 &kbase[(size_t)(jb + j)*NQKV_ + s8*8]);
        }
#pragma unroll
        for (int i = 0; i < 2; i++) {
            int idx = tid + 256 * i;
            int d = idx >> 3, s8 = idx & 7;
            cp16(sV + (uint32_t)(d*AROW + s8*16),
                 &vtb[(size_t)d * T_ + jb + s8*8]);
        }
    };

    const float SC = 0.125f * 1.44269504088896340736f;   // 1/sqrt(64)*log2(e)

    // Pair-balanced q-tile loop: heavy tile (NQT-1-bx) then light tile (bx).
#pragma unroll 1
    for (int sub = 0; sub < 2; sub++) {
        const int qb = sub ? (int)blockIdx.x : (NQT - 1 - (int)blockIdx.x);
        const int m0 = qb * 128;
        const __half* qbase = qkvh + ((size_t)b*T_ + m0)*NQKV_ + h*HD_;

        // Q tile (raw; softmax scale folded post-mma)
#pragma unroll
        for (int i = 0; i < 4; i++) {
            int idx = tid + 256 * i;
            int r = idx >> 3, s8 = idx & 7;
            cp16(sq + (uint32_t)(r*AROW + s8*16), &qbase[(size_t)r*NQKV_ + s8*8]);
        }
        issue(0); CP_COMMIT();

        float o[8][4];
        float mrow[2] = {MINIT, MINIT}, lrow[2] = {0.f, 0.f};
#pragma unroll
        for (int nt = 0; nt < 8; nt++)
#pragma unroll
            for (int c = 0; c < 4; c++) o[nt][c] = 0.f;

        const uint32_t qBase = sq + (uint32_t)(rb * AROW) + aLOff;
        const uint32_t pBase = sp + (uint32_t)(rb * AROW) + aLOff;

        const int nkv = 2*qb + 2;
        for (int kvb = 0; kvb < nkv; kvb++) {
            const int jb = kvb * 64;
            CP_WAIT0();
            __syncthreads();
            if (kvb + 1 < nkv) { issue(kvb + 1); CP_COMMIT(); }

            const uint32_t kBase = skv + (uint32_t)((kvb & 1) * AKV_TILE) * 2 + bLOff;
            const uint32_t vBase = kBase - bLOff + (uint32_t)AT_TILE * 2 + bLOff;

            if (jb > m0 + rb + 15) continue;

            // ---- S = Q @ K^T ----
            float s[8][4];
#pragma unroll
            for (int nt = 0; nt < 8; nt++)
#pragma unroll
                for (int c = 0; c < 4; c++) s[nt][c] = 0.f;

#pragma unroll
            for (int kk = 0; kk < 4; kk++) {
                uint32_t qa0, qa1, qa2, qa3;
                LDSM_X4(qa0, qa1, qa2, qa3, qBase + kk * 32);
#pragma unroll
                for (int ntp = 0; ntp < 4; ntp++) {
                    uint32_t k0, k1, k2, k3;
                    LDSM_X4(k0, k1, k2, k3,
                            kBase + (uint32_t)(ntp * 16 * AROW) + kk * 32);
                    MMA_F16(s[2*ntp],     qa0, qa1, qa2, qa3, k0, k1);
                    MMA_F16(s[2*ntp + 1], qa0, qa1, qa2, qa3, k2, k3);
                }
            }

            // ---- scale, causal mask (true j coords; K rows natural) ----
#pragma unroll
            for (int nt = 0; nt < 8; nt++)
#pragma unroll
                for (int c = 0; c < 4; c++) s[nt][c] *= SC;
            if (jb + 63 > m0 + rb) {
                const int r0 = m0 + rb + g, r1 = r0 + 8;
#pragma unroll
                for (int nt = 0; nt < 8; nt++) {
                    int cb = jb + nt*8 + 2*t4;
                    if (cb     > r0) s[nt][0] = MASKVAL;
                    if (cb + 1 > r0) s[nt][1] = MASKVAL;
                    if (cb     > r1) s[nt][2] = MASKVAL;
                    if (cb + 1 > r1) s[nt][3] = MASKVAL;
                }
            }

            // ---- online softmax (exp2 domain) ----
            float mx0 = MINIT, mx1 = MINIT;
#pragma unroll
            for (int nt = 0; nt < 8; nt++) {
                mx0 = fmaxf(mx0, fmaxf(s[nt][0], s[nt][1]));
                mx1 = fmaxf(mx1, fmaxf(s[nt][2], s[nt][3]));
            }
            mx0 = fmaxf(mx0, __shfl_xor_sync(0xffffffffu, mx0, 1));
            mx0 = fmaxf(mx0, __shfl_xor_sync(0xffffffffu, mx0, 2));
            mx1 = fmaxf(mx1, __shfl_xor_sync(0xffffffffu, mx1, 1));
            mx1 = fmaxf(mx1, __shfl_xor_sync(0xffffffffu, mx1, 2));
            const float mn0 = fmaxf(mrow[0], mx0), mn1 = fmaxf(mrow[1], mx1);
            const float al0 = ex2f(mrow[0] - mn0), al1 = ex2f(mrow[1] - mn1);
            mrow[0] = mn0; mrow[1] = mn1;

            float ls0 = 0.f, ls1 = 0.f;
            __half* p0 = Ps + (rb + g)*AH;
            __half* p1 = Ps + (rb + g + 8)*AH;
#pragma unroll
            for (int nt = 0; nt < 8; nt++) {
                s[nt][0] = ex2f(s[nt][0] - mn0);
                s[nt][1] = ex2f(s[nt][1] - mn0);
                s[nt][2] = ex2f(s[nt][2] - mn1);
                s[nt][3] = ex2f(s[nt][3] - mn1);
                ls0 += s[nt][0] + s[nt][1];
                ls1 += s[nt][2] + s[nt][3];
                o[nt][0] *= al0; o[nt][1] *= al0;
                o[nt][2] *= al1; o[nt][3] *= al1;
                // stage P half, pair-perm8 along j
                const int hoff = ((nt >> 1) << 4) + ((((t4 << 1) | (nt & 1))) << 1);
                *reinterpret_cast<__half2*>(p0 + hoff) =
                    __floats2half2_rn(s[nt][0], s[nt][1]);
                *reinterpret_cast<__half2*>(p1 + hoff) =
                    __floats2half2_rn(s[nt][2], s[nt][3]);
            }
            ls0 += __shfl_xor_sync(0xffffffffu, ls0, 1);
            ls0 += __shfl_xor_sync(0xffffffffu, ls0, 2);
            ls1 += __shfl_xor_sync(0xffffffffu, ls1, 1);
            ls1 += __shfl_xor_sync(0xffffffffu, ls1, 2);
            lrow[0] = lrow[0]*al0 + ls0;
            lrow[1] = lrow[1]*al1 + ls1;

            __syncwarp();

            // ---- O += P @ V^T ----
#pragma unroll
            for (int kk = 0; kk < 4; kk++) {
                uint32_t pa0, pa1, pa2, pa3;
                LDSM_X4(pa0, pa1, pa2, pa3, pBase + kk * 32);
#pragma unroll
                for (int ntp = 0; ntp < 4; ntp++) {
                    uint32_t v0, v1, v2, v3;
                    LDSM_X4(v0, v1, v2, v3,
                            vBase + (uint32_t)(ntp * 16 * AROW) + kk * 32);
                    MMA_F16(o[2*ntp],     pa0, pa1, pa2, pa3, v0, v1);
                    MMA_F16(o[2*ntp + 1], pa0, pa1, pa2, pa3, v2, v3);
                }
            }
        }

        // ---- epilogue: O columns are V^T-row positions == att layout ----
        const float inv0 = 1.0f / lrow[0], inv1 = 1.0f / lrow[1];
        const size_t r0 = (size_t)b*T_ + m0 + rb + g;
        const size_t r1 = r0 + 8;
#pragma unroll
        for (int nt = 0; nt < 8; nt++) {
            const int hc = h*HD_ + nt*8 + 2*t4;
            *reinterpret_cast<__half2*>(&att[r0*C_ + hc]) =
                __floats2half2_rn(o[nt][0] * inv0, o[nt][1] * inv0);
            *reinterpret_cast<__half2*>(&att[r1*C_ + hc]) =
                __floats2half2_rn(o[nt][2] * inv1, o[nt][3] * inv1);
        }

        __syncthreads();   // all warps done with Qs/KV0/Ps before next q-tile
    }
}

// ---------------------------------------------------------------------------
// Launch
// ---------------------------------------------------------------------------
extern "C" void kernel_launch(void* const* d_in, const int* in_sizes, int n_in,
                              void* d_out, int out_size) {
    const float* x     = (const float*)d_in[0];
    const float* Wqkv  = (const float*)d_in[1];
    const float* bqkv  = (const float*)d_in[2];
    const float* Wproj = (const float*)d_in[3];
    const float* bproj = (const float*)d_in[4];
    float* out = (float*)d_out;

    __half *qkvh_p, *vth_p, *att_p, *xh_p, *wq_p, *wp_p;
    cudaGetSymbolAddress((void**)&qkvh_p, g_qkvh);
    cudaGetSymbolAddress((void**)&vth_p,  g_vth);
    cudaGetSymbolAddress((void**)&att_p,  g_att);
    cudaGetSymbolAddress((void**)&xh_p,   g_xh);
    cudaGetSymbolAddress((void**)&wq_p,   g_wqkvh);
    cudaGetSymbolAddress((void**)&wp_p,   g_wprojh);

    cudaFuncSetAttribute(gemm_fp16<true>,
                         cudaFuncAttributeMaxDynamicSharedMemorySize, GEMM_SMEM);
    cudaFuncSetAttribute(gemm_fp16<false>,
                         cudaFuncAttributeMaxDynamicSharedMemorySize, GEMM_SMEM);
    cudaFuncSetAttribute(attn_fp16,
                         cudaFuncAttributeMaxDynamicSharedMemorySize, ATTN_SMEM);

    // 0) operand prep
    cvt_x_h<<<(M_*C_/16)/256, 256>>>((const float4*)x, (__half2*)xh_p, M_*C_/16);
    {
        dim3 blk(32, 8);
        dim3 gq(NQKV_/32, C_/32);
        cvt_transpose_h<<<gq, blk>>>(Wqkv, wq_p, C_, NQKV_);
        dim3 gp(C_/32, C_/32);
        cvt_transpose_h<<<gp, blk>>>(Wproj, wp_p, C_, C_);
    }

    // 1) QKV GEMM (fp16) -> half pair-perm8 qkv
    dim3 g1(NQKV_/128, M_/128);
    gemm_fp16<true><<<g1, 128, GEMM_SMEM>>>(xh_p, wq_p, bqkv, nullptr, qkvh_p,
                                            M_, NQKV_, C_);

    // 1b) V^T (pair-perm8 along t)
    {
        dim3 blk(32, 8);
        dim3 gv(C_/32, M_/32);
        vt_transpose<<<gv, blk>>>(qkvh_p, vth_p);
    }

    // 2) FP16 flash attention, pair-balanced single wave -> half att
    dim3 g2(T_/256, B_*NH_);    // 8 x 32 = 256 CTAs
    attn_fp16<<<g2, 256, ATTN_SMEM>>>(qkvh_p, vth_p, att_p);

    // 3) Output projection (fp16) -> natural fp32 out
    dim3 g3(C_/128, M_/128);
    gemm_fp16<false><<<g3, 128, GEMM_SMEM>>>(att_p, wp_p, bproj, out, nullptr,
                                             M_, C_, C_);
}